// round 1
// baseline (speedup 1.0000x reference)
#include <cuda_runtime.h>
#include <math.h>

// ---------------- problem constants ----------------
#define Bsz   32
#define NPIC  4
#define CCH   3
#define Him   224
#define Wim   224
#define PP    16
#define HP    14
#define SS    196            // patches per picture
#define DD    768            // hidden
#define ROWS  (Bsz*NPIC*SS)  // 25088
#define QROWS (Bsz*SS)       // 6272
#define NBATCH (Bsz*NPIC)    // 128

// ---------------- scratch (device globals; no allocation allowed) ----------
__device__ float g_p [ROWS*DD];
__device__ float g_h [ROWS*DD];
__device__ float g_Q [QROWS*DD];
__device__ float g_K [ROWS*DD];
__device__ float g_V [ROWS*DD];
__device__ float g_S [NBATCH*SS*SS];
__device__ float g_wv[ROWS*DD];
__device__ float g_t [ROWS*DD];

// ---------------- patchify ----------------
// p[b,n,s,d], s = i*14+j, d = c*256 + ph*16 + pw
__global__ void patchify_kernel(const float* __restrict__ x, float* __restrict__ p)
{
    long long idx = (long long)blockIdx.x * blockDim.x + threadIdx.x;
    long long total = (long long)ROWS * DD;
    if (idx >= total) return;
    int d   = (int)(idx % DD);
    int rest= (int)(idx / DD);
    int s   = rest % SS;
    int pic = rest / SS;           // b*4+n
    int c   = d >> 8;              // /256
    int rem = d & 255;
    int ph  = rem >> 4;
    int pw  = rem & 15;
    int i   = s / HP;
    int j   = s % HP;
    long long src = (((long long)pic * CCH + c) * Him + (i*PP + ph)) * Wim + (j*PP + pw);
    p[idx] = x[src];
}

// ---------------- generic tiled SGEMM ----------------
// C[M,N] = alpha * A(M,K) * B + bias, optional relu.
// transB==0: B is [K,N] row-major.  transB==1: B is [N,K] row-major (C = A B^T).
// Batched over blockIdx.z: A += (z/zdivA)*strideA, B += z*strideB, C += z*strideC.
// remapA: logical row r -> physical row (r/196)*784 + (r%196)   (picture-0 gather).
#define BM 128
#define BN 128
#define BK 8
__global__ __launch_bounds__(256, 2)
void sgemm_kernel(const float* __restrict__ A, const float* __restrict__ B,
                  const float* __restrict__ bias, float* __restrict__ C,
                  int M, int N, int K,
                  long long strideA, long long strideB, long long strideC,
                  int zdivA, float alpha, int relu, int transB, int remapA)
{
    __shared__ float As[BK][BM];
    __shared__ float Bs[BK][BN];

    const int z = blockIdx.z;
    A += (long long)(z / zdivA) * strideA;
    B += (long long)z * strideB;
    C += (long long)z * strideC;

    const int t  = threadIdx.x;
    const int tx = t & 15;
    const int ty = t >> 4;
    const int row0 = blockIdx.y * BM;
    const int col0 = blockIdx.x * BN;

    float acc[8][8];
#pragma unroll
    for (int i = 0; i < 8; i++)
#pragma unroll
        for (int j = 0; j < 8; j++) acc[i][j] = 0.f;

    // A-tile loader coords: 128 rows x 8 k, 4 elems/thread
    const int a_row = t >> 1;
    const int a_kb  = (t & 1) * 4;
    // B-tile loader coords
    const int bn_row = t >> 5;        // k index (notrans)
    const int bn_cb  = (t & 31) * 4;
    const int bt_n   = t >> 1;        // n index (trans)
    const int bt_kb  = (t & 1) * 4;

    for (int k0 = 0; k0 < K; k0 += BK) {
        // load A tile (transposed into As[k][m])
        {
            int rlog = row0 + a_row;
            bool rok = rlog < M;
            int rphys = rlog;
            if (remapA) rphys = (rlog / SS) * (NPIC*SS) + (rlog % SS);
            const float* Ar = A + (long long)rphys * K;
#pragma unroll
            for (int i = 0; i < 4; i++) {
                int kk = a_kb + i;
                float v = (rok && (k0 + kk) < K) ? Ar[k0 + kk] : 0.f;
                As[kk][a_row] = v;
            }
        }
        // load B tile into Bs[k][n]
        if (!transB) {
#pragma unroll
            for (int i = 0; i < 4; i++) {
                int n = bn_cb + i;
                float v = ((k0 + bn_row) < K && (col0 + n) < N)
                          ? B[(long long)(k0 + bn_row) * N + col0 + n] : 0.f;
                Bs[bn_row][n] = v;
            }
        } else {
#pragma unroll
            for (int i = 0; i < 4; i++) {
                int kk = bt_kb + i;
                float v = ((col0 + bt_n) < N && (k0 + kk) < K)
                          ? B[(long long)(col0 + bt_n) * K + k0 + kk] : 0.f;
                Bs[kk][bt_n] = v;
            }
        }
        __syncthreads();

#pragma unroll
        for (int kk = 0; kk < BK; kk++) {
            float a[8], b[8];
#pragma unroll
            for (int i = 0; i < 4; i++) {
                a[i]     = As[kk][ty*4 + i];
                a[i + 4] = As[kk][64 + ty*4 + i];
                b[i]     = Bs[kk][tx*4 + i];
                b[i + 4] = Bs[kk][64 + tx*4 + i];
            }
#pragma unroll
            for (int i = 0; i < 8; i++)
#pragma unroll
                for (int j = 0; j < 8; j++)
                    acc[i][j] += a[i] * b[j];
        }
        __syncthreads();
    }

    // epilogue
#pragma unroll
    for (int i = 0; i < 8; i++) {
        int r = row0 + ((i < 4) ? (ty*4 + i) : (64 + ty*4 + i - 4));
        if (r >= M) continue;
#pragma unroll
        for (int j = 0; j < 8; j++) {
            int c = col0 + ((j < 4) ? (tx*4 + j) : (64 + tx*4 + j - 4));
            if (c >= N) continue;
            float v = acc[i][j] * alpha;
            if (bias) v += bias[c];
            if (relu) v = fmaxf(v, 0.f);
            C[(long long)r * N + c] = v;
        }
    }
}

// ---------------- softmax over last dim (rows of length 196) ----------------
__global__ void softmax_kernel(float* __restrict__ S, int nrows)
{
    int warp = (blockIdx.x * blockDim.x + threadIdx.x) >> 5;
    int lane = threadIdx.x & 31;
    if (warp >= nrows) return;
    float* row = S + (long long)warp * SS;

    float v[7];
    float m = -INFINITY;
#pragma unroll
    for (int i = 0; i < 7; i++) {
        int c = lane + i*32;
        v[i] = (c < SS) ? row[c] : -INFINITY;
        m = fmaxf(m, v[i]);
    }
#pragma unroll
    for (int o = 16; o > 0; o >>= 1) m = fmaxf(m, __shfl_xor_sync(0xffffffffu, m, o));

    float sum = 0.f;
#pragma unroll
    for (int i = 0; i < 7; i++) {
        int c = lane + i*32;
        if (c < SS) { v[i] = __expf(v[i] - m); sum += v[i]; }
    }
#pragma unroll
    for (int o = 16; o > 0; o >>= 1) sum += __shfl_xor_sync(0xffffffffu, sum, o);
    float inv = 1.f / sum;
#pragma unroll
    for (int i = 0; i < 7; i++) {
        int c = lane + i*32;
        if (c < SS) row[c] = v[i] * inv;
    }
}

// ---------------- launch ----------------
static inline void launch_gemm(const float* A, const float* B, const float* bias,
                               float* C, int M, int N, int K,
                               long long sA, long long sB, long long sC,
                               int zdivA, int batches, float alpha,
                               int relu, int transB, int remapA)
{
    dim3 grid((N + BN - 1) / BN, (M + BM - 1) / BM, batches);
    sgemm_kernel<<<grid, 256>>>(A, B, bias, C, M, N, K, sA, sB, sC,
                                zdivA, alpha, relu, transB, remapA);
}

extern "C" void kernel_launch(void* const* d_in, const int* in_sizes, int n_in,
                              void* d_out, int out_size)
{
    const float* x   = (const float*)d_in[0];
    const float* W1  = (const float*)d_in[1];
    const float* b1  = (const float*)d_in[2];
    const float* Wq  = (const float*)d_in[3];
    const float* bq  = (const float*)d_in[4];
    const float* Wk  = (const float*)d_in[5];
    const float* bk  = (const float*)d_in[6];
    const float* Wv  = (const float*)d_in[7];
    const float* bv  = (const float*)d_in[8];
    const float* Wo1 = (const float*)d_in[9];
    const float* bo1 = (const float*)d_in[10];
    const float* Wo2 = (const float*)d_in[11];
    const float* bo2 = (const float*)d_in[12];
    float* out = (float*)d_out;

    float *p, *h, *Q, *K, *V, *S, *wv, *tbuf;
    cudaGetSymbolAddress((void**)&p,   g_p);
    cudaGetSymbolAddress((void**)&h,   g_h);
    cudaGetSymbolAddress((void**)&Q,   g_Q);
    cudaGetSymbolAddress((void**)&K,   g_K);
    cudaGetSymbolAddress((void**)&V,   g_V);
    cudaGetSymbolAddress((void**)&S,   g_S);
    cudaGetSymbolAddress((void**)&wv,  g_wv);
    cudaGetSymbolAddress((void**)&tbuf,g_t);

    // 1. patchify
    {
        long long total = (long long)ROWS * DD;
        int threads = 256;
        long long blocks = (total + threads - 1) / threads;
        patchify_kernel<<<(unsigned)blocks, threads>>>(x, p);
    }
    // 2. h = p @ W1 + b1
    launch_gemm(p, W1, b1, h, ROWS, DD, DD, 0, 0, 0, 1, 1, 1.f, 0, 0, 0);
    // 3. Q = h[:,0] @ Wq + bq   (row remap gathers picture-0 rows)
    launch_gemm(h, Wq, bq, Q, QROWS, DD, DD, 0, 0, 0, 1, 1, 1.f, 0, 0, 1);
    // 4. K = h @ Wk + bk ; V = h @ Wv + bv
    launch_gemm(h, Wk, bk, K, ROWS, DD, DD, 0, 0, 0, 1, 1, 1.f, 0, 0, 0);
    launch_gemm(h, Wv, bv, V, ROWS, DD, DD, 0, 0, 0, 1, 1, 1.f, 0, 0, 0);
    // 5. scores = scale * Q @ K^T   (batched over 128 = b*4+n; Q shared per b)
    {
        float scale = 1.f / sqrtf((float)DD);
        launch_gemm(Q, K, nullptr, S, SS, SS, DD,
                    (long long)SS*DD, (long long)SS*DD, (long long)SS*SS,
                    NPIC, NBATCH, scale, 0, 1, 0);
    }
    // 6. softmax rows
    {
        int nrows = NBATCH * SS;
        int warpsPerBlock = 8;
        int blocks = (nrows + warpsPerBlock - 1) / warpsPerBlock;
        softmax_kernel<<<blocks, warpsPerBlock * 32>>>(S, nrows);
    }
    // 7. wv = attn @ V  (batched)
    launch_gemm(S, V, nullptr, wv, SS, DD, SS,
                (long long)SS*SS, (long long)SS*DD, (long long)SS*DD,
                1, NBATCH, 1.f, 0, 0, 0);
    // 8. t = relu(wv @ Wo1 + bo1)
    launch_gemm(wv, Wo1, bo1, tbuf, ROWS, DD, DD, 0, 0, 0, 1, 1, 1.f, 1, 0, 0);
    // 9. out = t @ Wo2 + bo2
    launch_gemm(tbuf, Wo2, bo2, out, ROWS, DD, DD, 0, 0, 0, 1, 1, 1.f, 0, 0, 0);
}

// round 3
// speedup vs baseline: 2.3094x; 2.3094x over previous
#include <cuda_runtime.h>
#include <cuda_bf16.h>
#include <stdint.h>
#include <math.h>

// ================= problem constants =================
#define Bsz   32
#define NPIC  4
#define CCH   3
#define Him   224
#define Wim   224
#define PPs   16
#define HPn   14
#define SSn   196
#define DDn   768
#define ROWS  (Bsz*NPIC*SSn)   // 25088
#define QROWS (Bsz*SSn)        // 6272
#define NBat  (Bsz*NPIC)       // 128
#define KPAD  256

// ================= device scratch =================
__device__ __align__(1024) __nv_bfloat16 g_phi [ROWS*DDn],  g_plo [ROWS*DDn];
__device__ __align__(1024) __nv_bfloat16 g_wthi[6*DDn*DDn], g_wtlo[6*DDn*DDn];
__device__ __align__(1024) __nv_bfloat16 g_hhi [ROWS*DDn],  g_hlo [ROWS*DDn];
__device__ __align__(1024) __nv_bfloat16 g_qhi [QROWS*DDn], g_qlo [QROWS*DDn];
__device__ __align__(1024) __nv_bfloat16 g_khi [ROWS*DDn],  g_klo [ROWS*DDn];
__device__ __align__(1024) float         g_v   [ROWS*DDn];
__device__ __align__(1024) __nv_bfloat16 g_vthi[NBat*DDn*KPAD], g_vtlo[NBat*DDn*KPAD];
__device__ __align__(1024) float         g_sc  [NBat*SSn*SSn];
__device__ __align__(1024) __nv_bfloat16 g_athi[NBat*SSn*KPAD], g_atlo[NBat*SSn*KPAD];
__device__ __align__(1024) __nv_bfloat16 g_wvhi[ROWS*DDn], g_wvlo[ROWS*DDn];
__device__ __align__(1024) __nv_bfloat16 g_thi [ROWS*DDn], g_tlo [ROWS*DDn];

// ================= helpers =================
__device__ __forceinline__ uint32_t smem_u32(const void* p){
    uint32_t a;
    asm("{ .reg .u64 t; cvta.to.shared.u64 t, %1; cvt.u32.u64 %0, t; }" : "=r"(a) : "l"(p));
    return a;
}
#define SWZ128(o) ((o) ^ (((o) >> 3) & 0x70))

__device__ __forceinline__ void cp16(uint32_t dst, const void* src, int nbytes){
    asm volatile("cp.async.cg.shared.global [%0], [%1], 16, %2;"
                 :: "r"(dst), "l"(src), "r"(nbytes) : "memory");
}
__device__ __forceinline__ void cp_commit(){ asm volatile("cp.async.commit_group;" ::: "memory"); }
__device__ __forceinline__ void cp_wait1(){  asm volatile("cp.async.wait_group 1;" ::: "memory"); }

__device__ __forceinline__ void ldsm4(uint32_t& r0,uint32_t& r1,uint32_t& r2,uint32_t& r3,uint32_t a){
    asm volatile("ldmatrix.sync.aligned.m8n8.x4.shared.b16 {%0,%1,%2,%3}, [%4];"
        : "=r"(r0),"=r"(r1),"=r"(r2),"=r"(r3) : "r"(a));
}
__device__ __forceinline__ void mma16816(float* c, const uint32_t* a, const uint32_t* b){
    asm volatile("mma.sync.aligned.m16n8k16.row.col.f32.bf16.bf16.f32 "
        "{%0,%1,%2,%3}, {%4,%5,%6,%7}, {%8,%9}, {%0,%1,%2,%3};"
        : "+f"(c[0]),"+f"(c[1]),"+f"(c[2]),"+f"(c[3])
        : "r"(a[0]),"r"(a[1]),"r"(a[2]),"r"(a[3]), "r"(b[0]),"r"(b[1]));
}
__device__ __forceinline__ void split2(float v, __nv_bfloat16& h, __nv_bfloat16& l){
    h = __float2bfloat16(v);
    l = __float2bfloat16(v - __bfloat162float(h));
}

// ================= patchify + split =================
__global__ void patchify_split(const float* __restrict__ x,
                               __nv_bfloat16* __restrict__ phi,
                               __nv_bfloat16* __restrict__ plo)
{
    long long idx = (long long)blockIdx.x * blockDim.x + threadIdx.x;
    long long total = (long long)ROWS * DDn;
    if (idx >= total) return;
    int d    = (int)(idx % DDn);
    int rest = (int)(idx / DDn);
    int s    = rest % SSn;
    int pic  = rest / SSn;
    int c  = d >> 8;
    int rm = d & 255;
    int ph = rm >> 4;
    int pw = rm & 15;
    int i = s / HPn, j = s % HPn;
    long long src = (((long long)pic * CCH + c) * Him + (i*PPs + ph)) * Wim + (j*PPs + pw);
    split2(x[src], phi[idx], plo[idx]);
}

// ================= weight transpose + split =================
__global__ void wtrans_split(const float* __restrict__ W,
                             __nv_bfloat16* __restrict__ whi,
                             __nv_bfloat16* __restrict__ wlo)
{
    int idx = blockIdx.x * blockDim.x + threadIdx.x;
    if (idx >= DDn*DDn) return;
    int n = idx / DDn, k = idx % DDn;
    split2(W[k*DDn + n], whi[idx], wlo[idx]);
}

// ================= V transpose + split =================
__global__ void vtrans_split(const float* __restrict__ V,
                             __nv_bfloat16* __restrict__ vthi,
                             __nv_bfloat16* __restrict__ vtlo)
{
    __shared__ float tile[32][33];
    int z  = blockIdx.z;
    int d0 = blockIdx.x * 32;
    int s0 = blockIdx.y * 32;
    int tx = threadIdx.x, ty = threadIdx.y;
    for (int sy = ty; sy < 32; sy += 8) {
        int s = s0 + sy, d = d0 + tx;
        tile[sy][tx] = (s < SSn) ? V[((long long)z*SSn + s)*DDn + d] : 0.f;
    }
    __syncthreads();
    for (int dy = ty; dy < 32; dy += 8) {
        int d = d0 + dy, s = s0 + tx;
        long long o = ((long long)z*DDn + d)*KPAD + s;
        split2(tile[tx][dy], vthi[o], vtlo[o]);
    }
}

// ================= softmax + split (196 -> padded 256) =================
__global__ void softmax_split(const float* __restrict__ S,
                              __nv_bfloat16* __restrict__ ahi,
                              __nv_bfloat16* __restrict__ alo)
{
    int warp = (blockIdx.x * blockDim.x + threadIdx.x) >> 5;
    int lane = threadIdx.x & 31;
    if (warp >= NBat*SSn) return;
    const float* row = S + (long long)warp * SSn;
    float v[7];
    float m = -INFINITY;
#pragma unroll
    for (int i = 0; i < 7; i++) {
        int c = lane + i*32;
        v[i] = (c < SSn) ? row[c] : -INFINITY;
        m = fmaxf(m, v[i]);
    }
#pragma unroll
    for (int o = 16; o > 0; o >>= 1) m = fmaxf(m, __shfl_xor_sync(0xffffffffu, m, o));
    float sum = 0.f;
#pragma unroll
    for (int i = 0; i < 7; i++) {
        int c = lane + i*32;
        if (c < SSn) { v[i] = __expf(v[i] - m); sum += v[i]; } else v[i] = 0.f;
    }
#pragma unroll
    for (int o = 16; o > 0; o >>= 1) sum += __shfl_xor_sync(0xffffffffu, sum, o);
    float inv = 1.f / sum;
    __nv_bfloat16* oh = ahi + (long long)warp * KPAD;
    __nv_bfloat16* ol = alo + (long long)warp * KPAD;
#pragma unroll
    for (int i = 0; i < 8; i++) {
        int c = lane + i*32;
        float val = (i < 7 && c < SSn) ? v[i] * inv : 0.f;
        split2(val, oh[c], ol[c]);
    }
}

// ================= mma.sync split-bf16 GEMM =================
// D[M, Nvalid] = alpha * A * B^T (+bias)(relu).  3 passes: AhBh + AhBl + AlBh.
#define BMt 128
#define BNt 128
#define BKt 64
#define NTHR 256
#define STG  16384                     // 128 rows * 128 bytes
#define DSM  (4*STG + 1024)

__global__ void __launch_bounds__(NTHR)
mm_gemm(const __nv_bfloat16* __restrict__ Ah, const __nv_bfloat16* __restrict__ Al,
        const __nv_bfloat16* __restrict__ Bh, const __nv_bfloat16* __restrict__ Bl,
        const float* __restrict__ bias,
        float* __restrict__ Cf, __nv_bfloat16* __restrict__ Ch, __nv_bfloat16* __restrict__ Cl,
        int M, int Nvalid, int K, int ldA, int ldB, int ldC,
        long long sA, long long sB, long long sC, int zdivA,
        float alpha, int relu, int remapA)
{
    extern __shared__ char dsm[];
    uint32_t dyn  = smem_u32(dsm);
    uint32_t base = (dyn + 1023u) & ~1023u;
    const uint32_t sAo[2] = { base,         base + STG };
    const uint32_t sBo[2] = { base + 2*STG, base + 3*STG };

    const int t = threadIdx.x, lane = t & 31, w = t >> 5;
    const int wm = w & 1, wn = w >> 1;          // warp grid 2 (M) x 4 (N)
    const int z = blockIdx.z;
    const int m0 = blockIdx.y * BMt;
    const int n0 = blockIdx.x * BNt;

    const __nv_bfloat16* Ahz = Ah + (long long)(z / zdivA) * sA;
    const __nv_bfloat16* Alz = Al + (long long)(z / zdivA) * sA;
    const __nv_bfloat16* Bhz = Bh + (long long)z * sB;
    const __nv_bfloat16* Blz = Bl + (long long)z * sB;
    float* Cfz = Cf ? Cf + (long long)z * sC : nullptr;
    __nv_bfloat16* Chz = Ch ? Ch + (long long)z * sC : nullptr;
    __nv_bfloat16* Clz = Cl ? Cl + (long long)z * sC : nullptr;

    float acc[4][4][4];
#pragma unroll
    for (int a = 0; a < 4; a++)
#pragma unroll
        for (int b = 0; b < 4; b++)
#pragma unroll
            for (int c = 0; c < 4; c++) acc[a][b][c] = 0.f;

    const int ktiles = K / BKt;
    const int ITERS  = 3 * ktiles;

    // ---- tile loader (A and B tiles are both 128 rows x 128 bytes) ----
#define LOAD_TILE(ITN, BUF)                                                          \
    {                                                                                \
        int pass = (ITN) / ktiles;                                                   \
        int k0   = ((ITN) - pass * ktiles) * BKt;                                    \
        const __nv_bfloat16* As = (pass < 2) ? Ahz : Alz;                            \
        const __nv_bfloat16* Bs = (pass == 1) ? Blz : Bhz;                           \
        _Pragma("unroll")                                                            \
        for (int i = 0; i < 4; i++) {                                                \
            int flat = t + i*256;                                                    \
            int row = flat >> 3, c = flat & 7;                                       \
            int gr = m0 + row;                                                       \
            int ok = gr < M;                                                         \
            long long pr = 0;                                                        \
            if (ok) pr = remapA ? (long long)gr + (gr/SSn)*(NPIC*SSn - SSn)          \
                                : (long long)gr;                                     \
            cp16(sAo[BUF] + SWZ128((uint32_t)(row*128 + c*16)),                      \
                 As + pr*ldA + k0 + c*8, ok ? 16 : 0);                               \
        }                                                                            \
        _Pragma("unroll")                                                            \
        for (int i = 0; i < 4; i++) {                                                \
            int flat = t + i*256;                                                    \
            int row = flat >> 3, c = flat & 7;                                       \
            int gn = n0 + row;                                                       \
            int ok = gn < Nvalid;                                                    \
            cp16(sBo[BUF] + SWZ128((uint32_t)(row*128 + c*16)),                      \
                 Bs + (long long)(ok ? gn : 0)*ldB + k0 + c*8, ok ? 16 : 0);         \
        }                                                                            \
    }

    LOAD_TILE(0, 0);
    cp_commit();

    const int rl = lane & 15, hh = lane >> 4;

    for (int itn = 0; itn < ITERS; itn++) {
        int buf = itn & 1;
        if (itn + 1 < ITERS) LOAD_TILE(itn + 1, buf ^ 1);
        cp_commit();
        cp_wait1();
        __syncthreads();

        uint32_t sa = sAo[buf], sb = sBo[buf];
#pragma unroll
        for (int ks = 0; ks < 4; ks++) {
            uint32_t af[4][4], bf2[4][2];
            int c = ks*2 + hh;
#pragma unroll
            for (int mt = 0; mt < 4; mt++) {
                int row = wm*64 + mt*16 + rl;
                ldsm4(af[mt][0], af[mt][1], af[mt][2], af[mt][3],
                      sa + SWZ128((uint32_t)(row*128 + c*16)));
            }
#pragma unroll
            for (int bt = 0; bt < 2; bt++) {
                uint32_t r0, r1, r2, r3;
                int row = wn*32 + bt*16 + rl;
                ldsm4(r0, r1, r2, r3, sb + SWZ128((uint32_t)(row*128 + c*16)));
                bf2[bt*2][0]   = r0;  bf2[bt*2][1]   = r2;
                bf2[bt*2+1][0] = r1;  bf2[bt*2+1][1] = r3;
            }
#pragma unroll
            for (int mt = 0; mt < 4; mt++)
#pragma unroll
                for (int nt = 0; nt < 4; nt++)
                    mma16816(acc[mt][nt], af[mt], bf2[nt]);
        }
        __syncthreads();
    }

    // ---- epilogue ----
    const int r0l = lane >> 2, cl = (lane & 3) * 2;
#pragma unroll
    for (int mt = 0; mt < 4; mt++) {
#pragma unroll
        for (int nt = 0; nt < 4; nt++) {
            int gc = n0 + wn*32 + nt*8 + cl;
#pragma unroll
            for (int half = 0; half < 2; half++) {
                int gr = m0 + wm*64 + mt*16 + r0l + half*8;
                if (gr >= M) continue;
                float v0 = acc[mt][nt][half*2 + 0] * alpha;
                float v1 = acc[mt][nt][half*2 + 1] * alpha;
                if (bias) { v0 += __ldg(bias + gc); v1 += __ldg(bias + gc + 1); }
                if (relu) { v0 = fmaxf(v0, 0.f); v1 = fmaxf(v1, 0.f); }
                long long o = (long long)gr * ldC + gc;
                if (gc < Nvalid) {
                    if (Cfz) Cfz[o] = v0;
                    if (Chz) { __nv_bfloat16 h; __nv_bfloat16 l; split2(v0, h, l);
                               Chz[o] = h; Clz[o] = l; }
                }
                if (gc + 1 < Nvalid) {
                    if (Cfz) Cfz[o+1] = v1;
                    if (Chz) { __nv_bfloat16 h; __nv_bfloat16 l; split2(v1, h, l);
                               Chz[o+1] = h; Clz[o+1] = l; }
                }
            }
        }
    }
}

// ================= host side =================
static void gemm(const __nv_bfloat16* Ah, const __nv_bfloat16* Al,
                 const __nv_bfloat16* Bh, const __nv_bfloat16* Bl,
                 const float* bias, float* Cf, __nv_bfloat16* Ch, __nv_bfloat16* Cl,
                 int M, int Nvalid, int K, int ldA, int ldB, int ldC,
                 long long sA, long long sB, long long sC, int zdivA, int nz,
                 float alpha, int relu, int remapA)
{
    dim3 g((Nvalid + BNt - 1)/BNt, (M + BMt - 1)/BMt, nz);
    mm_gemm<<<g, NTHR, DSM>>>(Ah, Al, Bh, Bl, bias, Cf, Ch, Cl,
                              M, Nvalid, K, ldA, ldB, ldC, sA, sB, sC,
                              zdivA, alpha, relu, remapA);
}

extern "C" void kernel_launch(void* const* d_in, const int* in_sizes, int n_in,
                              void* d_out, int out_size)
{
    const float* x   = (const float*)d_in[0];
    const float* W1  = (const float*)d_in[1];
    const float* b1  = (const float*)d_in[2];
    const float* Wq  = (const float*)d_in[3];
    const float* bq  = (const float*)d_in[4];
    const float* Wk  = (const float*)d_in[5];
    const float* bk  = (const float*)d_in[6];
    const float* Wv  = (const float*)d_in[7];
    const float* bv  = (const float*)d_in[8];
    const float* Wo1 = (const float*)d_in[9];
    const float* bo1 = (const float*)d_in[10];
    const float* Wo2 = (const float*)d_in[11];
    const float* bo2 = (const float*)d_in[12];
    float* out = (float*)d_out;

    cudaFuncSetAttribute(mm_gemm, cudaFuncAttributeMaxDynamicSharedMemorySize, DSM);

    __nv_bfloat16 *phi,*plo,*wthi,*wtlo,*hhi,*hlo,*qhi,*qlo,*khi,*klo;
    __nv_bfloat16 *vthi,*vtlo,*athi,*atlo,*wvhi,*wvlo,*thi,*tlo;
    float *v, *sc;
    cudaGetSymbolAddress((void**)&phi,  g_phi);  cudaGetSymbolAddress((void**)&plo,  g_plo);
    cudaGetSymbolAddress((void**)&wthi, g_wthi); cudaGetSymbolAddress((void**)&wtlo, g_wtlo);
    cudaGetSymbolAddress((void**)&hhi,  g_hhi);  cudaGetSymbolAddress((void**)&hlo,  g_hlo);
    cudaGetSymbolAddress((void**)&qhi,  g_qhi);  cudaGetSymbolAddress((void**)&qlo,  g_qlo);
    cudaGetSymbolAddress((void**)&khi,  g_khi);  cudaGetSymbolAddress((void**)&klo,  g_klo);
    cudaGetSymbolAddress((void**)&v,    g_v);
    cudaGetSymbolAddress((void**)&vthi, g_vthi); cudaGetSymbolAddress((void**)&vtlo, g_vtlo);
    cudaGetSymbolAddress((void**)&sc,   g_sc);
    cudaGetSymbolAddress((void**)&athi, g_athi); cudaGetSymbolAddress((void**)&atlo, g_atlo);
    cudaGetSymbolAddress((void**)&wvhi, g_wvhi); cudaGetSymbolAddress((void**)&wvlo, g_wvlo);
    cudaGetSymbolAddress((void**)&thi,  g_thi);  cudaGetSymbolAddress((void**)&tlo,  g_tlo);

    // 1. patchify
    {
        long long total = (long long)ROWS * DDn;
        patchify_split<<<(unsigned)((total + 255)/256), 256>>>(x, phi, plo);
    }
    // 2. weight transpose + split
    {
        int nthr = DDn*DDn, blocks = (nthr + 255)/256;
        wtrans_split<<<blocks,256>>>(W1,  wthi + 0*DDn*DDn, wtlo + 0*DDn*DDn);
        wtrans_split<<<blocks,256>>>(Wq,  wthi + 1*DDn*DDn, wtlo + 1*DDn*DDn);
        wtrans_split<<<blocks,256>>>(Wk,  wthi + 2*DDn*DDn, wtlo + 2*DDn*DDn);
        wtrans_split<<<blocks,256>>>(Wv,  wthi + 3*DDn*DDn, wtlo + 3*DDn*DDn);
        wtrans_split<<<blocks,256>>>(Wo1, wthi + 4*DDn*DDn, wtlo + 4*DDn*DDn);
        wtrans_split<<<blocks,256>>>(Wo2, wthi + 5*DDn*DDn, wtlo + 5*DDn*DDn);
    }
    // 3. h = p @ W1 + b1
    gemm(phi, plo, wthi + 0*DDn*DDn, wtlo + 0*DDn*DDn, b1,
         nullptr, hhi, hlo, ROWS, DDn, DDn, DDn, DDn, DDn, 0,0,0, 1,1, 1.f, 0, 0);
    // 4. Q = h[:,0] @ Wq + bq (remap)
    gemm(hhi, hlo, wthi + 1*DDn*DDn, wtlo + 1*DDn*DDn, bq,
         nullptr, qhi, qlo, QROWS, DDn, DDn, DDn, DDn, DDn, 0,0,0, 1,1, 1.f, 0, 1);
    // 5. K = h @ Wk + bk
    gemm(hhi, hlo, wthi + 2*DDn*DDn, wtlo + 2*DDn*DDn, bk,
         nullptr, khi, klo, ROWS, DDn, DDn, DDn, DDn, DDn, 0,0,0, 1,1, 1.f, 0, 0);
    // 6. V = h @ Wv + bv (fp32)
    gemm(hhi, hlo, wthi + 3*DDn*DDn, wtlo + 3*DDn*DDn, bv,
         v, nullptr, nullptr, ROWS, DDn, DDn, DDn, DDn, DDn, 0,0,0, 1,1, 1.f, 0, 0);
    // 7. V transpose -> Vt [z][768][256]
    {
        dim3 g(DDn/32, KPAD/32, NBat), b(32, 8);
        vtrans_split<<<g, b>>>(v, vthi, vtlo);
    }
    // 8. scores = scale * Q @ K^T (batched)
    {
        float scale = 1.f / sqrtf((float)DDn);
        gemm(qhi, qlo, khi, klo, nullptr, sc, nullptr, nullptr,
             SSn, SSn, DDn, DDn, DDn, SSn,
             (long long)SSn*DDn, (long long)SSn*DDn, (long long)SSn*SSn,
             NPIC, NBat, scale, 0, 0);
    }
    // 9. softmax -> attn hi/lo (padded 256)
    {
        int nrows = NBat * SSn;
        softmax_split<<<(nrows + 7)/8, 8*32>>>(sc, athi, atlo);
    }
    // 10. wv = attn @ V (B = Vt)
    gemm(athi, atlo, vthi, vtlo, nullptr, nullptr, wvhi, wvlo,
         SSn, DDn, KPAD, KPAD, KPAD, DDn,
         (long long)SSn*KPAD, (long long)DDn*KPAD, (long long)SSn*DDn,
         1, NBat, 1.f, 0, 0);
    // 11. t = relu(wv @ Wo1 + bo1)
    gemm(wvhi, wvlo, wthi + 4*DDn*DDn, wtlo + 4*DDn*DDn, bo1,
         nullptr, thi, tlo, ROWS, DDn, DDn, DDn, DDn, DDn, 0,0,0, 1,1, 1.f, 1, 0);
    // 12. out = t @ Wo2 + bo2
    gemm(thi, tlo, wthi + 5*DDn*DDn, wtlo + 5*DDn*DDn, bo2,
         out, nullptr, nullptr, ROWS, DDn, DDn, DDn, DDn, DDn, 0,0,0, 1,1, 1.f, 0, 0);
}

// round 4
// speedup vs baseline: 2.3453x; 1.0155x over previous
#include <cuda_runtime.h>
#include <cuda_bf16.h>
#include <stdint.h>
#include <math.h>

// ================= problem constants =================
#define Bsz   32
#define NPIC  4
#define CCH   3
#define Him   224
#define Wim   224
#define PPs   16
#define HPn   14
#define SSn   196
#define DDn   768
#define ROWS  (Bsz*NPIC*SSn)   // 25088
#define QROWS (Bsz*SSn)        // 6272
#define NBat  (Bsz*NPIC)       // 128
#define KPAD  256

// ================= device scratch =================
__device__ __align__(1024) __nv_bfloat16 g_phi [ROWS*DDn],  g_plo [ROWS*DDn];
__device__ __align__(1024) __nv_bfloat16 g_wthi[6*DDn*DDn], g_wtlo[6*DDn*DDn];
__device__ __align__(1024) __nv_bfloat16 g_hhi [ROWS*DDn],  g_hlo [ROWS*DDn];
__device__ __align__(1024) __nv_bfloat16 g_qhi [QROWS*DDn], g_qlo [QROWS*DDn];
__device__ __align__(1024) __nv_bfloat16 g_khi [ROWS*DDn],  g_klo [ROWS*DDn];
__device__ __align__(1024) float         g_v   [ROWS*DDn];
__device__ __align__(1024) __nv_bfloat16 g_vthi[NBat*DDn*KPAD], g_vtlo[NBat*DDn*KPAD];
__device__ __align__(1024) float         g_sc  [NBat*SSn*SSn];
__device__ __align__(1024) __nv_bfloat16 g_athi[NBat*SSn*KPAD], g_atlo[NBat*SSn*KPAD];
__device__ __align__(1024) __nv_bfloat16 g_wvhi[ROWS*DDn], g_wvlo[ROWS*DDn];
__device__ __align__(1024) __nv_bfloat16 g_thi [ROWS*DDn], g_tlo [ROWS*DDn];

// ================= helpers =================
__device__ __forceinline__ uint32_t smem_u32(const void* p){
    uint32_t a;
    asm("{ .reg .u64 t; cvta.to.shared.u64 t, %1; cvt.u32.u64 %0, t; }" : "=r"(a) : "l"(p));
    return a;
}
#define SWZ128(o) ((o) ^ (((o) >> 3) & 0x70))

__device__ __forceinline__ void cp16(uint32_t dst, const void* src, int nbytes){
    asm volatile("cp.async.cg.shared.global [%0], [%1], 16, %2;"
                 :: "r"(dst), "l"(src), "r"(nbytes) : "memory");
}
__device__ __forceinline__ void cp_commit(){ asm volatile("cp.async.commit_group;" ::: "memory"); }
__device__ __forceinline__ void cp_wait1(){  asm volatile("cp.async.wait_group 1;" ::: "memory"); }

__device__ __forceinline__ void ldsm4(uint32_t& r0,uint32_t& r1,uint32_t& r2,uint32_t& r3,uint32_t a){
    asm volatile("ldmatrix.sync.aligned.m8n8.x4.shared.b16 {%0,%1,%2,%3}, [%4];"
        : "=r"(r0),"=r"(r1),"=r"(r2),"=r"(r3) : "r"(a));
}
__device__ __forceinline__ void mma16816(float* c, const uint32_t* a, const uint32_t* b){
    asm volatile("mma.sync.aligned.m16n8k16.row.col.f32.bf16.bf16.f32 "
        "{%0,%1,%2,%3}, {%4,%5,%6,%7}, {%8,%9}, {%0,%1,%2,%3};"
        : "+f"(c[0]),"+f"(c[1]),"+f"(c[2]),"+f"(c[3])
        : "r"(a[0]),"r"(a[1]),"r"(a[2]),"r"(a[3]), "r"(b[0]),"r"(b[1]));
}
__device__ __forceinline__ void split2(float v, __nv_bfloat16& h, __nv_bfloat16& l){
    h = __float2bfloat16(v);
    l = __float2bfloat16(v - __bfloat162float(h));
}

// ================= patchify + split =================
__global__ void patchify_split(const float* __restrict__ x,
                               __nv_bfloat16* __restrict__ phi,
                               __nv_bfloat16* __restrict__ plo)
{
    long long idx = (long long)blockIdx.x * blockDim.x + threadIdx.x;
    long long total = (long long)ROWS * DDn;
    if (idx >= total) return;
    int d    = (int)(idx % DDn);
    int rest = (int)(idx / DDn);
    int s    = rest % SSn;
    int pic  = rest / SSn;
    int c  = d >> 8;
    int rm = d & 255;
    int ph = rm >> 4;
    int pw = rm & 15;
    int i = s / HPn, j = s % HPn;
    long long src = (((long long)pic * CCH + c) * Him + (i*PPs + ph)) * Wim + (j*PPs + pw);
    split2(x[src], phi[idx], plo[idx]);
}

// ================= weight transpose + split =================
__global__ void wtrans_split(const float* __restrict__ W,
                             __nv_bfloat16* __restrict__ whi,
                             __nv_bfloat16* __restrict__ wlo)
{
    int idx = blockIdx.x * blockDim.x + threadIdx.x;
    if (idx >= DDn*DDn) return;
    int n = idx / DDn, k = idx % DDn;
    split2(W[k*DDn + n], whi[idx], wlo[idx]);
}

// ================= V transpose + split =================
__global__ void vtrans_split(const float* __restrict__ V,
                             __nv_bfloat16* __restrict__ vthi,
                             __nv_bfloat16* __restrict__ vtlo)
{
    __shared__ float tile[32][33];
    int z  = blockIdx.z;
    int d0 = blockIdx.x * 32;
    int s0 = blockIdx.y * 32;
    int tx = threadIdx.x, ty = threadIdx.y;
    for (int sy = ty; sy < 32; sy += 8) {
        int s = s0 + sy, d = d0 + tx;
        tile[sy][tx] = (s < SSn) ? V[((long long)z*SSn + s)*DDn + d] : 0.f;
    }
    __syncthreads();
    for (int dy = ty; dy < 32; dy += 8) {
        int d = d0 + dy, s = s0 + tx;
        long long o = ((long long)z*DDn + d)*KPAD + s;
        split2(tile[tx][dy], vthi[o], vtlo[o]);
    }
}

// ================= softmax + split (196 -> padded 256) =================
__global__ void softmax_split(const float* __restrict__ S,
                              __nv_bfloat16* __restrict__ ahi,
                              __nv_bfloat16* __restrict__ alo)
{
    int warp = (blockIdx.x * blockDim.x + threadIdx.x) >> 5;
    int lane = threadIdx.x & 31;
    if (warp >= NBat*SSn) return;
    const float* row = S + (long long)warp * SSn;
    float v[7];
    float m = -INFINITY;
#pragma unroll
    for (int i = 0; i < 7; i++) {
        int c = lane + i*32;
        v[i] = (c < SSn) ? row[c] : -INFINITY;
        m = fmaxf(m, v[i]);
    }
#pragma unroll
    for (int o = 16; o > 0; o >>= 1) m = fmaxf(m, __shfl_xor_sync(0xffffffffu, m, o));
    float sum = 0.f;
#pragma unroll
    for (int i = 0; i < 7; i++) {
        int c = lane + i*32;
        if (c < SSn) { v[i] = __expf(v[i] - m); sum += v[i]; } else v[i] = 0.f;
    }
#pragma unroll
    for (int o = 16; o > 0; o >>= 1) sum += __shfl_xor_sync(0xffffffffu, sum, o);
    float inv = 1.f / sum;
    __nv_bfloat16* oh = ahi + (long long)warp * KPAD;
    __nv_bfloat16* ol = alo + (long long)warp * KPAD;
#pragma unroll
    for (int i = 0; i < 8; i++) {
        int c = lane + i*32;
        float val = (i < 7 && c < SSn) ? v[i] * inv : 0.f;
        split2(val, oh[c], ol[c]);
    }
}

// ================= mma.sync split-bf16 GEMM (combined-tile, 3 passes) ======
// D = alpha * A * B^T (+bias)(relu). Per k-tile: load Ah,Al,Bh,Bl once, run
// AhBh + AhBl + AlBh from resident smem.
#define BMt 128
#define BNt 128
#define BKt 64
#define NTHR 256
#define TILEB 16384                    // one 128x128B sub-tile
#define STG4  (4*TILEB)                // Ah|Al|Bh|Bl = 64KB per stage
#define DSM   (2*STG4 + 1024)

__global__ void __launch_bounds__(NTHR)
mm_gemm(const __nv_bfloat16* __restrict__ Ah, const __nv_bfloat16* __restrict__ Al,
        const __nv_bfloat16* __restrict__ Bh, const __nv_bfloat16* __restrict__ Bl,
        const float* __restrict__ bias,
        float* __restrict__ Cf, __nv_bfloat16* __restrict__ Ch, __nv_bfloat16* __restrict__ Cl,
        int M, int Nvalid, int K, int ldA, int ldB, int ldC,
        long long sA, long long sB, long long sC, int zdivA,
        float alpha, int relu, int remapA)
{
    extern __shared__ char dsm[];
    uint32_t dyn  = smem_u32(dsm);
    uint32_t base = (dyn + 1023u) & ~1023u;
    const uint32_t stg[2] = { base, base + STG4 };

    const int t = threadIdx.x, lane = t & 31, w = t >> 5;
    const int wm = w & 1, wn = w >> 1;          // warp grid 2 (M) x 4 (N)
    const int z = blockIdx.z;
    const int m0 = blockIdx.y * BMt;
    const int n0 = blockIdx.x * BNt;

    const __nv_bfloat16* Ahz = Ah + (long long)(z / zdivA) * sA;
    const __nv_bfloat16* Alz = Al + (long long)(z / zdivA) * sA;
    const __nv_bfloat16* Bhz = Bh + (long long)z * sB;
    const __nv_bfloat16* Blz = Bl + (long long)z * sB;
    float* Cfz = Cf ? Cf + (long long)z * sC : nullptr;
    __nv_bfloat16* Chz = Ch ? Ch + (long long)z * sC : nullptr;
    __nv_bfloat16* Clz = Cl ? Cl + (long long)z * sC : nullptr;

    float acc[4][4][4];
#pragma unroll
    for (int a = 0; a < 4; a++)
#pragma unroll
        for (int b = 0; b < 4; b++)
#pragma unroll
            for (int c = 0; c < 4; c++) acc[a][b][c] = 0.f;

    const int ITERS = K / BKt;

    // ---- stage loader: Ah, Al, Bh, Bl sub-tiles for one k0 ----
#define LOAD_STAGE(ITN, BUF)                                                         \
    {                                                                                \
        int k0 = (ITN) * BKt;                                                        \
        _Pragma("unroll")                                                            \
        for (int j = 0; j < 4; j++) {                                                \
            int flat = t + j*256;                                                    \
            int row = flat >> 3, cc = flat & 7;                                      \
            uint32_t so = SWZ128((uint32_t)(row*128 + cc*16));                       \
            int gr = m0 + row;                                                       \
            int ok = gr < M;                                                         \
            long long pr = 0;                                                        \
            if (ok) pr = remapA ? (long long)gr + (gr/SSn)*(NPIC*SSn - SSn)          \
                                : (long long)gr;                                     \
            cp16(stg[BUF] + 0*TILEB + so, Ahz + pr*ldA + k0 + cc*8, ok ? 16 : 0);    \
            cp16(stg[BUF] + 1*TILEB + so, Alz + pr*ldA + k0 + cc*8, ok ? 16 : 0);    \
            int gn = n0 + row;                                                       \
            int okb = gn < Nvalid;                                                   \
            long long pn = okb ? gn : 0;                                             \
            cp16(stg[BUF] + 2*TILEB + so, Bhz + pn*ldB + k0 + cc*8, okb ? 16 : 0);   \
            cp16(stg[BUF] + 3*TILEB + so, Blz + pn*ldB + k0 + cc*8, okb ? 16 : 0);   \
        }                                                                            \
    }

    LOAD_STAGE(0, 0);
    cp_commit();

    const int rl = lane & 15, hh = lane >> 4;

    for (int itn = 0; itn < ITERS; itn++) {
        int buf = itn & 1;
        if (itn + 1 < ITERS) LOAD_STAGE(itn + 1, buf ^ 1);
        cp_commit();
        cp_wait1();
        __syncthreads();

        uint32_t sAH = stg[buf] + 0*TILEB, sAL = stg[buf] + 1*TILEB;
        uint32_t sBH = stg[buf] + 2*TILEB, sBL = stg[buf] + 3*TILEB;
#pragma unroll
        for (int ks = 0; ks < 4; ks++) {
            int c = ks*2 + hh;
            uint32_t aH[4][4], aL[4][4], bH[4][2], bL[4][2];
#pragma unroll
            for (int mt = 0; mt < 4; mt++) {
                int row = wm*64 + mt*16 + rl;
                uint32_t so = SWZ128((uint32_t)(row*128 + c*16));
                ldsm4(aH[mt][0], aH[mt][1], aH[mt][2], aH[mt][3], sAH + so);
                ldsm4(aL[mt][0], aL[mt][1], aL[mt][2], aL[mt][3], sAL + so);
            }
#pragma unroll
            for (int bt = 0; bt < 2; bt++) {
                int row = wn*32 + bt*16 + rl;
                uint32_t so = SWZ128((uint32_t)(row*128 + c*16));
                uint32_t r0, r1, r2, r3;
                ldsm4(r0, r1, r2, r3, sBH + so);
                bH[bt*2][0]   = r0;  bH[bt*2][1]   = r2;
                bH[bt*2+1][0] = r1;  bH[bt*2+1][1] = r3;
                ldsm4(r0, r1, r2, r3, sBL + so);
                bL[bt*2][0]   = r0;  bL[bt*2][1]   = r2;
                bL[bt*2+1][0] = r1;  bL[bt*2+1][1] = r3;
            }
#pragma unroll
            for (int mt = 0; mt < 4; mt++)
#pragma unroll
                for (int nt = 0; nt < 4; nt++)
                    mma16816(acc[mt][nt], aH[mt], bH[nt]);
#pragma unroll
            for (int mt = 0; mt < 4; mt++)
#pragma unroll
                for (int nt = 0; nt < 4; nt++)
                    mma16816(acc[mt][nt], aH[mt], bL[nt]);
#pragma unroll
            for (int mt = 0; mt < 4; mt++)
#pragma unroll
                for (int nt = 0; nt < 4; nt++)
                    mma16816(acc[mt][nt], aL[mt], bH[nt]);
        }
        __syncthreads();
    }

    // ---- epilogue ----
    const int r0l = lane >> 2, cl = (lane & 3) * 2;
#pragma unroll
    for (int mt = 0; mt < 4; mt++) {
#pragma unroll
        for (int nt = 0; nt < 4; nt++) {
            int gc = n0 + wn*32 + nt*8 + cl;
#pragma unroll
            for (int half = 0; half < 2; half++) {
                int gr = m0 + wm*64 + mt*16 + r0l + half*8;
                if (gr >= M) continue;
                float v0 = acc[mt][nt][half*2 + 0] * alpha;
                float v1 = acc[mt][nt][half*2 + 1] * alpha;
                if (bias) { v0 += __ldg(bias + gc); v1 += __ldg(bias + gc + 1); }
                if (relu) { v0 = fmaxf(v0, 0.f); v1 = fmaxf(v1, 0.f); }
                long long o = (long long)gr * ldC + gc;
                if (gc < Nvalid) {
                    if (Cfz) Cfz[o] = v0;
                    if (Chz) { __nv_bfloat16 h, l; split2(v0, h, l);
                               Chz[o] = h; Clz[o] = l; }
                }
                if (gc + 1 < Nvalid) {
                    if (Cfz) Cfz[o+1] = v1;
                    if (Chz) { __nv_bfloat16 h, l; split2(v1, h, l);
                               Chz[o+1] = h; Clz[o+1] = l; }
                }
            }
        }
    }
}

// ================= host side =================
static void gemm(const __nv_bfloat16* Ah, const __nv_bfloat16* Al,
                 const __nv_bfloat16* Bh, const __nv_bfloat16* Bl,
                 const float* bias, float* Cf, __nv_bfloat16* Ch, __nv_bfloat16* Cl,
                 int M, int Nvalid, int K, int ldA, int ldB, int ldC,
                 long long sA, long long sB, long long sC, int zdivA, int nz,
                 float alpha, int relu, int remapA)
{
    dim3 g((Nvalid + BNt - 1)/BNt, (M + BMt - 1)/BMt, nz);
    mm_gemm<<<g, NTHR, DSM>>>(Ah, Al, Bh, Bl, bias, Cf, Ch, Cl,
                              M, Nvalid, K, ldA, ldB, ldC, sA, sB, sC,
                              zdivA, alpha, relu, remapA);
}

extern "C" void kernel_launch(void* const* d_in, const int* in_sizes, int n_in,
                              void* d_out, int out_size)
{
    const float* x   = (const float*)d_in[0];
    const float* W1  = (const float*)d_in[1];
    const float* b1  = (const float*)d_in[2];
    const float* Wq  = (const float*)d_in[3];
    const float* bq  = (const float*)d_in[4];
    const float* Wk  = (const float*)d_in[5];
    const float* bk  = (const float*)d_in[6];
    const float* Wv  = (const float*)d_in[7];
    const float* bv  = (const float*)d_in[8];
    const float* Wo1 = (const float*)d_in[9];
    const float* bo1 = (const float*)d_in[10];
    const float* Wo2 = (const float*)d_in[11];
    const float* bo2 = (const float*)d_in[12];
    float* out = (float*)d_out;

    cudaFuncSetAttribute(mm_gemm, cudaFuncAttributeMaxDynamicSharedMemorySize, DSM);

    __nv_bfloat16 *phi,*plo,*wthi,*wtlo,*hhi,*hlo,*qhi,*qlo,*khi,*klo;
    __nv_bfloat16 *vthi,*vtlo,*athi,*atlo,*wvhi,*wvlo,*thi,*tlo;
    float *v, *sc;
    cudaGetSymbolAddress((void**)&phi,  g_phi);  cudaGetSymbolAddress((void**)&plo,  g_plo);
    cudaGetSymbolAddress((void**)&wthi, g_wthi); cudaGetSymbolAddress((void**)&wtlo, g_wtlo);
    cudaGetSymbolAddress((void**)&hhi,  g_hhi);  cudaGetSymbolAddress((void**)&hlo,  g_hlo);
    cudaGetSymbolAddress((void**)&qhi,  g_qhi);  cudaGetSymbolAddress((void**)&qlo,  g_qlo);
    cudaGetSymbolAddress((void**)&khi,  g_khi);  cudaGetSymbolAddress((void**)&klo,  g_klo);
    cudaGetSymbolAddress((void**)&v,    g_v);
    cudaGetSymbolAddress((void**)&vthi, g_vthi); cudaGetSymbolAddress((void**)&vtlo, g_vtlo);
    cudaGetSymbolAddress((void**)&sc,   g_sc);
    cudaGetSymbolAddress((void**)&athi, g_athi); cudaGetSymbolAddress((void**)&atlo, g_atlo);
    cudaGetSymbolAddress((void**)&wvhi, g_wvhi); cudaGetSymbolAddress((void**)&wvlo, g_wvlo);
    cudaGetSymbolAddress((void**)&thi,  g_thi);  cudaGetSymbolAddress((void**)&tlo,  g_tlo);

    // 1. patchify
    {
        long long total = (long long)ROWS * DDn;
        patchify_split<<<(unsigned)((total + 255)/256), 256>>>(x, phi, plo);
    }
    // 2. weight transpose + split
    {
        int nthr = DDn*DDn, blocks = (nthr + 255)/256;
        wtrans_split<<<blocks,256>>>(W1,  wthi + 0*DDn*DDn, wtlo + 0*DDn*DDn);
        wtrans_split<<<blocks,256>>>(Wq,  wthi + 1*DDn*DDn, wtlo + 1*DDn*DDn);
        wtrans_split<<<blocks,256>>>(Wk,  wthi + 2*DDn*DDn, wtlo + 2*DDn*DDn);
        wtrans_split<<<blocks,256>>>(Wv,  wthi + 3*DDn*DDn, wtlo + 3*DDn*DDn);
        wtrans_split<<<blocks,256>>>(Wo1, wthi + 4*DDn*DDn, wtlo + 4*DDn*DDn);
        wtrans_split<<<blocks,256>>>(Wo2, wthi + 5*DDn*DDn, wtlo + 5*DDn*DDn);
    }
    // 3. h = p @ W1 + b1
    gemm(phi, plo, wthi + 0*DDn*DDn, wtlo + 0*DDn*DDn, b1,
         nullptr, hhi, hlo, ROWS, DDn, DDn, DDn, DDn, DDn, 0,0,0, 1,1, 1.f, 0, 0);
    // 4. Q = h[:,0] @ Wq + bq (remap)
    gemm(hhi, hlo, wthi + 1*DDn*DDn, wtlo + 1*DDn*DDn, bq,
         nullptr, qhi, qlo, QROWS, DDn, DDn, DDn, DDn, DDn, 0,0,0, 1,1, 1.f, 0, 1);
    // 5. K = h @ Wk + bk
    gemm(hhi, hlo, wthi + 2*DDn*DDn, wtlo + 2*DDn*DDn, bk,
         nullptr, khi, klo, ROWS, DDn, DDn, DDn, DDn, DDn, 0,0,0, 1,1, 1.f, 0, 0);
    // 6. V = h @ Wv + bv (fp32)
    gemm(hhi, hlo, wthi + 3*DDn*DDn, wtlo + 3*DDn*DDn, bv,
         v, nullptr, nullptr, ROWS, DDn, DDn, DDn, DDn, DDn, 0,0,0, 1,1, 1.f, 0, 0);
    // 7. V transpose -> Vt [z][768][256]
    {
        dim3 g(DDn/32, KPAD/32, NBat), b(32, 8);
        vtrans_split<<<g, b>>>(v, vthi, vtlo);
    }
    // 8. scores = scale * Q @ K^T (batched)
    {
        float scale = 1.f / sqrtf((float)DDn);
        gemm(qhi, qlo, khi, klo, nullptr, sc, nullptr, nullptr,
             SSn, SSn, DDn, DDn, DDn, SSn,
             (long long)SSn*DDn, (long long)SSn*DDn, (long long)SSn*SSn,
             NPIC, NBat, scale, 0, 0);
    }
    // 9. softmax -> attn hi/lo (padded 256)
    {
        int nrows = NBat * SSn;
        softmax_split<<<(nrows + 7)/8, 8*32>>>(sc, athi, atlo);
    }
    // 10. wv = attn @ V (B = Vt)
    gemm(athi, atlo, vthi, vtlo, nullptr, nullptr, wvhi, wvlo,
         SSn, DDn, KPAD, KPAD, KPAD, DDn,
         (long long)SSn*KPAD, (long long)DDn*KPAD, (long long)SSn*DDn,
         1, NBat, 1.f, 0, 0);
    // 11. t = relu(wv @ Wo1 + bo1)
    gemm(wvhi, wvlo, wthi + 4*DDn*DDn, wtlo + 4*DDn*DDn, bo1,
         nullptr, thi, tlo, ROWS, DDn, DDn, DDn, DDn, DDn, 0,0,0, 1,1, 1.f, 1, 0);
    // 12. out = t @ Wo2 + bo2
    gemm(thi, tlo, wthi + 5*DDn*DDn, wtlo + 5*DDn*DDn, bo2,
         out, nullptr, nullptr, ROWS, DDn, DDn, DDn, DDn, DDn, 0,0,0, 1,1, 1.f, 0, 0);
}

// round 5
// speedup vs baseline: 2.5014x; 1.0666x over previous
#include <cuda_runtime.h>
#include <cuda_bf16.h>
#include <stdint.h>
#include <math.h>

// ================= problem constants =================
#define Bsz   32
#define NPIC  4
#define CCH   3
#define Him   224
#define Wim   224
#define PPs   16
#define HPn   14
#define SSn   196
#define DDn   768
#define ROWS  (Bsz*NPIC*SSn)   // 25088
#define QROWS (Bsz*SSn)        // 6272
#define NBat  (Bsz*NPIC)       // 128
#define KPAD  256

// ================= device scratch =================
__device__ __align__(1024) __nv_bfloat16 g_phi [ROWS*DDn],  g_plo [ROWS*DDn];
__device__ __align__(1024) __nv_bfloat16 g_wthi[6*DDn*DDn], g_wtlo[6*DDn*DDn];
__device__ __align__(1024) __nv_bfloat16 g_hhi [ROWS*DDn],  g_hlo [ROWS*DDn];
__device__ __align__(1024) __nv_bfloat16 g_qhi [QROWS*DDn], g_qlo [QROWS*DDn];
__device__ __align__(1024) __nv_bfloat16 g_khi [ROWS*DDn],  g_klo [ROWS*DDn];
__device__ __align__(1024) float         g_v   [ROWS*DDn];
__device__ __align__(1024) __nv_bfloat16 g_vthi[NBat*DDn*KPAD], g_vtlo[NBat*DDn*KPAD];
__device__ __align__(1024) float         g_sc  [NBat*SSn*SSn];
__device__ __align__(1024) __nv_bfloat16 g_athi[NBat*SSn*KPAD], g_atlo[NBat*SSn*KPAD];
__device__ __align__(1024) __nv_bfloat16 g_wvhi[ROWS*DDn], g_wvlo[ROWS*DDn];
__device__ __align__(1024) __nv_bfloat16 g_thi [ROWS*DDn], g_tlo [ROWS*DDn];

// ================= helpers =================
__device__ __forceinline__ uint32_t smem_u32(const void* p){
    uint32_t a;
    asm("{ .reg .u64 t; cvta.to.shared.u64 t, %1; cvt.u32.u64 %0, t; }" : "=r"(a) : "l"(p));
    return a;
}
#define SWZ128(o) ((o) ^ (((o) >> 3) & 0x70))

__device__ __forceinline__ void cp16(uint32_t dst, const void* src, int nbytes){
    asm volatile("cp.async.cg.shared.global [%0], [%1], 16, %2;"
                 :: "r"(dst), "l"(src), "r"(nbytes) : "memory");
}
__device__ __forceinline__ void cp_commit(){ asm volatile("cp.async.commit_group;" ::: "memory"); }
__device__ __forceinline__ void cp_wait1(){  asm volatile("cp.async.wait_group 1;" ::: "memory"); }

__device__ __forceinline__ void ldsm4(uint32_t& r0,uint32_t& r1,uint32_t& r2,uint32_t& r3,uint32_t a){
    asm volatile("ldmatrix.sync.aligned.m8n8.x4.shared.b16 {%0,%1,%2,%3}, [%4];"
        : "=r"(r0),"=r"(r1),"=r"(r2),"=r"(r3) : "r"(a));
}
__device__ __forceinline__ void mma16816(float* c, const uint32_t* a, const uint32_t* b){
    asm volatile("mma.sync.aligned.m16n8k16.row.col.f32.bf16.bf16.f32 "
        "{%0,%1,%2,%3}, {%4,%5,%6,%7}, {%8,%9}, {%0,%1,%2,%3};"
        : "+f"(c[0]),"+f"(c[1]),"+f"(c[2]),"+f"(c[3])
        : "r"(a[0]),"r"(a[1]),"r"(a[2]),"r"(a[3]), "r"(b[0]),"r"(b[1]));
}
__device__ __forceinline__ void split2(float v, __nv_bfloat16& h, __nv_bfloat16& l){
    h = __float2bfloat16(v);
    l = __float2bfloat16(v - __bfloat162float(h));
}

// ================= patchify + split =================
__global__ void patchify_split(const float* __restrict__ x,
                               __nv_bfloat16* __restrict__ phi,
                               __nv_bfloat16* __restrict__ plo)
{
    long long idx = (long long)blockIdx.x * blockDim.x + threadIdx.x;
    long long total = (long long)ROWS * DDn;
    if (idx >= total) return;
    int d    = (int)(idx % DDn);
    int rest = (int)(idx / DDn);
    int s    = rest % SSn;
    int pic  = rest / SSn;
    int c  = d >> 8;
    int rm = d & 255;
    int ph = rm >> 4;
    int pw = rm & 15;
    int i = s / HPn, j = s % HPn;
    long long src = (((long long)pic * CCH + c) * Him + (i*PPs + ph)) * Wim + (j*PPs + pw);
    split2(x[src], phi[idx], plo[idx]);
}

// ================= weight transpose + split =================
__global__ void wtrans_split(const float* __restrict__ W,
                             __nv_bfloat16* __restrict__ whi,
                             __nv_bfloat16* __restrict__ wlo)
{
    int idx = blockIdx.x * blockDim.x + threadIdx.x;
    if (idx >= DDn*DDn) return;
    int n = idx / DDn, k = idx % DDn;
    split2(W[k*DDn + n], whi[idx], wlo[idx]);
}

// ================= V transpose + split =================
__global__ void vtrans_split(const float* __restrict__ V,
                             __nv_bfloat16* __restrict__ vthi,
                             __nv_bfloat16* __restrict__ vtlo)
{
    __shared__ float tile[32][33];
    int z  = blockIdx.z;
    int d0 = blockIdx.x * 32;
    int s0 = blockIdx.y * 32;
    int tx = threadIdx.x, ty = threadIdx.y;
    for (int sy = ty; sy < 32; sy += 8) {
        int s = s0 + sy, d = d0 + tx;
        tile[sy][tx] = (s < SSn) ? V[((long long)z*SSn + s)*DDn + d] : 0.f;
    }
    __syncthreads();
    for (int dy = ty; dy < 32; dy += 8) {
        int d = d0 + dy, s = s0 + tx;
        long long o = ((long long)z*DDn + d)*KPAD + s;
        split2(tile[tx][dy], vthi[o], vtlo[o]);
    }
}

// ================= softmax + split (196 -> padded 256) =================
__global__ void softmax_split(const float* __restrict__ S,
                              __nv_bfloat16* __restrict__ ahi,
                              __nv_bfloat16* __restrict__ alo)
{
    int warp = (blockIdx.x * blockDim.x + threadIdx.x) >> 5;
    int lane = threadIdx.x & 31;
    if (warp >= NBat*SSn) return;
    const float* row = S + (long long)warp * SSn;
    float v[7];
    float m = -INFINITY;
#pragma unroll
    for (int i = 0; i < 7; i++) {
        int c = lane + i*32;
        v[i] = (c < SSn) ? row[c] : -INFINITY;
        m = fmaxf(m, v[i]);
    }
#pragma unroll
    for (int o = 16; o > 0; o >>= 1) m = fmaxf(m, __shfl_xor_sync(0xffffffffu, m, o));
    float sum = 0.f;
#pragma unroll
    for (int i = 0; i < 7; i++) {
        int c = lane + i*32;
        if (c < SSn) { v[i] = __expf(v[i] - m); sum += v[i]; } else v[i] = 0.f;
    }
#pragma unroll
    for (int o = 16; o > 0; o >>= 1) sum += __shfl_xor_sync(0xffffffffu, sum, o);
    float inv = 1.f / sum;
    __nv_bfloat16* oh = ahi + (long long)warp * KPAD;
    __nv_bfloat16* ol = alo + (long long)warp * KPAD;
#pragma unroll
    for (int i = 0; i < 8; i++) {
        int c = lane + i*32;
        float val = (i < 7 && c < SSn) ? v[i] * inv : 0.f;
        split2(val, oh[c], ol[c]);
    }
}

// ================= mma.sync split-bf16 GEMM (128x256 tile, 3 passes) ======
#define BMt 128
#define BNt 256
#define BKt 64
#define NTHR 256
#define TILEA 16384                    // 128 rows * 128B
#define TILEB 32768                    // 256 rows * 128B
#define STGSZ (2*TILEA + 2*TILEB)      // Ah|Al|Bh|Bl = 96KB
#define DSM   (2*STGSZ + 1024)

__global__ void __launch_bounds__(NTHR)
mm_gemm(const __nv_bfloat16* __restrict__ Ah, const __nv_bfloat16* __restrict__ Al,
        const __nv_bfloat16* __restrict__ Bh, const __nv_bfloat16* __restrict__ Bl,
        const float* __restrict__ bias,
        float* __restrict__ Cf, __nv_bfloat16* __restrict__ Ch, __nv_bfloat16* __restrict__ Cl,
        int M, int Nvalid, int K, int ldA, int ldB, int ldC,
        long long sA, long long sB, long long sC, int zdivA,
        float alpha, int relu, int remapA)
{
    extern __shared__ char dsm[];
    uint32_t dyn  = smem_u32(dsm);
    uint32_t base = (dyn + 1023u) & ~1023u;
    const uint32_t stg[2] = { base, base + STGSZ };

    const int t = threadIdx.x, lane = t & 31, w = t >> 5;
    const int wm = w & 1, wn = w >> 1;          // warp grid 2 (M) x 4 (N); warp tile 64x64
    const int z = blockIdx.z;
    const int m0 = blockIdx.y * BMt;
    const int n0 = blockIdx.x * BNt;

    const __nv_bfloat16* Ahz = Ah + (long long)(z / zdivA) * sA;
    const __nv_bfloat16* Alz = Al + (long long)(z / zdivA) * sA;
    const __nv_bfloat16* Bhz = Bh + (long long)z * sB;
    const __nv_bfloat16* Blz = Bl + (long long)z * sB;
    float* Cfz = Cf ? Cf + (long long)z * sC : nullptr;
    __nv_bfloat16* Chz = Ch ? Ch + (long long)z * sC : nullptr;
    __nv_bfloat16* Clz = Cl ? Cl + (long long)z * sC : nullptr;

    float acc[4][8][4];
#pragma unroll
    for (int a = 0; a < 4; a++)
#pragma unroll
        for (int b = 0; b < 8; b++)
#pragma unroll
            for (int c = 0; c < 4; c++) acc[a][b][c] = 0.f;

    const int ITERS = K / BKt;

    // ---- stage loader: Ah, Al (128x128B), Bh, Bl (256x128B) for one k0 ----
#define LOAD_STAGE(ITN, BUF)                                                         \
    {                                                                                \
        int k0 = (ITN) * BKt;                                                        \
        _Pragma("unroll")                                                            \
        for (int j = 0; j < 4; j++) {                                                \
            int flat = t + j*256;                                                    \
            int row = flat >> 3, cc = flat & 7;                                      \
            uint32_t so = SWZ128((uint32_t)(row*128 + cc*16));                       \
            int gr = m0 + row;                                                       \
            int ok = gr < M;                                                         \
            long long pr = 0;                                                        \
            if (ok) pr = remapA ? (long long)gr + (gr/SSn)*(NPIC*SSn - SSn)          \
                                : (long long)gr;                                     \
            cp16(stg[BUF] + 0*TILEA + so, Ahz + pr*ldA + k0 + cc*8, ok ? 16 : 0);    \
            cp16(stg[BUF] + 1*TILEA + so, Alz + pr*ldA + k0 + cc*8, ok ? 16 : 0);    \
        }                                                                            \
        _Pragma("unroll")                                                            \
        for (int j = 0; j < 8; j++) {                                                \
            int flat = t + j*256;                                                    \
            int row = flat >> 3, cc = flat & 7;                                      \
            uint32_t so = SWZ128((uint32_t)(row*128 + cc*16));                       \
            int gn = n0 + row;                                                       \
            int okb = gn < Nvalid;                                                   \
            long long pn = okb ? gn : 0;                                             \
            cp16(stg[BUF] + 2*TILEA + so, Bhz + pn*ldB + k0 + cc*8, okb ? 16 : 0);   \
            cp16(stg[BUF] + 2*TILEA + TILEB + so, Blz + pn*ldB + k0 + cc*8,          \
                 okb ? 16 : 0);                                                      \
        }                                                                            \
    }

    LOAD_STAGE(0, 0);
    cp_commit();

    const int rl = lane & 15, hh = lane >> 4;

    for (int itn = 0; itn < ITERS; itn++) {
        int buf = itn & 1;
        if (itn + 1 < ITERS) LOAD_STAGE(itn + 1, buf ^ 1);
        cp_commit();
        cp_wait1();
        __syncthreads();

        uint32_t sAH = stg[buf] + 0*TILEA, sAL = stg[buf] + 1*TILEA;
        uint32_t sBH = stg[buf] + 2*TILEA, sBL = stg[buf] + 2*TILEA + TILEB;
#pragma unroll
        for (int ks = 0; ks < 4; ks++) {
            int c = ks*2 + hh;
            uint32_t aH[4][4], aL[4][4], bH[8][2], bL[8][2];
#pragma unroll
            for (int mt = 0; mt < 4; mt++) {
                int row = wm*64 + mt*16 + rl;
                uint32_t so = SWZ128((uint32_t)(row*128 + c*16));
                ldsm4(aH[mt][0], aH[mt][1], aH[mt][2], aH[mt][3], sAH + so);
                ldsm4(aL[mt][0], aL[mt][1], aL[mt][2], aL[mt][3], sAL + so);
            }
#pragma unroll
            for (int bt = 0; bt < 4; bt++) {
                int row = wn*64 + bt*16 + rl;
                uint32_t so = SWZ128((uint32_t)(row*128 + c*16));
                uint32_t r0, r1, r2, r3;
                ldsm4(r0, r1, r2, r3, sBH + so);
                bH[bt*2][0]   = r0;  bH[bt*2][1]   = r2;
                bH[bt*2+1][0] = r1;  bH[bt*2+1][1] = r3;
                ldsm4(r0, r1, r2, r3, sBL + so);
                bL[bt*2][0]   = r0;  bL[bt*2][1]   = r2;
                bL[bt*2+1][0] = r1;  bL[bt*2+1][1] = r3;
            }
#pragma unroll
            for (int mt = 0; mt < 4; mt++)
#pragma unroll
                for (int nt = 0; nt < 8; nt++)
                    mma16816(acc[mt][nt], aH[mt], bH[nt]);
#pragma unroll
            for (int mt = 0; mt < 4; mt++)
#pragma unroll
                for (int nt = 0; nt < 8; nt++)
                    mma16816(acc[mt][nt], aH[mt], bL[nt]);
#pragma unroll
            for (int mt = 0; mt < 4; mt++)
#pragma unroll
                for (int nt = 0; nt < 8; nt++)
                    mma16816(acc[mt][nt], aL[mt], bH[nt]);
        }
        __syncthreads();
    }

    // ---- epilogue ----
    const int r0l = lane >> 2, cl = (lane & 3) * 2;
#pragma unroll
    for (int mt = 0; mt < 4; mt++) {
#pragma unroll
        for (int nt = 0; nt < 8; nt++) {
            int gc = n0 + wn*64 + nt*8 + cl;
#pragma unroll
            for (int half = 0; half < 2; half++) {
                int gr = m0 + wm*64 + mt*16 + r0l + half*8;
                if (gr >= M) continue;
                float v0 = acc[mt][nt][half*2 + 0] * alpha;
                float v1 = acc[mt][nt][half*2 + 1] * alpha;
                if (bias) { v0 += __ldg(bias + gc); v1 += __ldg(bias + gc + 1); }
                if (relu) { v0 = fmaxf(v0, 0.f); v1 = fmaxf(v1, 0.f); }
                long long o = (long long)gr * ldC + gc;
                if (gc < Nvalid) {
                    if (Cfz) Cfz[o] = v0;
                    if (Chz) { __nv_bfloat16 h, l; split2(v0, h, l);
                               Chz[o] = h; Clz[o] = l; }
                }
                if (gc + 1 < Nvalid) {
                    if (Cfz) Cfz[o+1] = v1;
                    if (Chz) { __nv_bfloat16 h, l; split2(v1, h, l);
                               Chz[o+1] = h; Clz[o+1] = l; }
                }
            }
        }
    }
}

// ================= host side =================
static void gemm(const __nv_bfloat16* Ah, const __nv_bfloat16* Al,
                 const __nv_bfloat16* Bh, const __nv_bfloat16* Bl,
                 const float* bias, float* Cf, __nv_bfloat16* Ch, __nv_bfloat16* Cl,
                 int M, int Nvalid, int K, int ldA, int ldB, int ldC,
                 long long sA, long long sB, long long sC, int zdivA, int nz,
                 float alpha, int relu, int remapA)
{
    dim3 g((Nvalid + BNt - 1)/BNt, (M + BMt - 1)/BMt, nz);
    mm_gemm<<<g, NTHR, DSM>>>(Ah, Al, Bh, Bl, bias, Cf, Ch, Cl,
                              M, Nvalid, K, ldA, ldB, ldC, sA, sB, sC,
                              zdivA, alpha, relu, remapA);
}

extern "C" void kernel_launch(void* const* d_in, const int* in_sizes, int n_in,
                              void* d_out, int out_size)
{
    const float* x   = (const float*)d_in[0];
    const float* W1  = (const float*)d_in[1];
    const float* b1  = (const float*)d_in[2];
    const float* Wq  = (const float*)d_in[3];
    const float* bq  = (const float*)d_in[4];
    const float* Wk  = (const float*)d_in[5];
    const float* bk  = (const float*)d_in[6];
    const float* Wv  = (const float*)d_in[7];
    const float* bv  = (const float*)d_in[8];
    const float* Wo1 = (const float*)d_in[9];
    const float* bo1 = (const float*)d_in[10];
    const float* Wo2 = (const float*)d_in[11];
    const float* bo2 = (const float*)d_in[12];
    float* out = (float*)d_out;

    cudaFuncSetAttribute(mm_gemm, cudaFuncAttributeMaxDynamicSharedMemorySize, DSM);

    __nv_bfloat16 *phi,*plo,*wthi,*wtlo,*hhi,*hlo,*qhi,*qlo,*khi,*klo;
    __nv_bfloat16 *vthi,*vtlo,*athi,*atlo,*wvhi,*wvlo,*thi,*tlo;
    float *v, *sc;
    cudaGetSymbolAddress((void**)&phi,  g_phi);  cudaGetSymbolAddress((void**)&plo,  g_plo);
    cudaGetSymbolAddress((void**)&wthi, g_wthi); cudaGetSymbolAddress((void**)&wtlo, g_wtlo);
    cudaGetSymbolAddress((void**)&hhi,  g_hhi);  cudaGetSymbolAddress((void**)&hlo,  g_hlo);
    cudaGetSymbolAddress((void**)&qhi,  g_qhi);  cudaGetSymbolAddress((void**)&qlo,  g_qlo);
    cudaGetSymbolAddress((void**)&khi,  g_khi);  cudaGetSymbolAddress((void**)&klo,  g_klo);
    cudaGetSymbolAddress((void**)&v,    g_v);
    cudaGetSymbolAddress((void**)&vthi, g_vthi); cudaGetSymbolAddress((void**)&vtlo, g_vtlo);
    cudaGetSymbolAddress((void**)&sc,   g_sc);
    cudaGetSymbolAddress((void**)&athi, g_athi); cudaGetSymbolAddress((void**)&atlo, g_atlo);
    cudaGetSymbolAddress((void**)&wvhi, g_wvhi); cudaGetSymbolAddress((void**)&wvlo, g_wvlo);
    cudaGetSymbolAddress((void**)&thi,  g_thi);  cudaGetSymbolAddress((void**)&tlo,  g_tlo);

    // 1. patchify
    {
        long long total = (long long)ROWS * DDn;
        patchify_split<<<(unsigned)((total + 255)/256), 256>>>(x, phi, plo);
    }
    // 2. weight transpose + split
    {
        int nthr = DDn*DDn, blocks = (nthr + 255)/256;
        wtrans_split<<<blocks,256>>>(W1,  wthi + 0*DDn*DDn, wtlo + 0*DDn*DDn);
        wtrans_split<<<blocks,256>>>(Wq,  wthi + 1*DDn*DDn, wtlo + 1*DDn*DDn);
        wtrans_split<<<blocks,256>>>(Wk,  wthi + 2*DDn*DDn, wtlo + 2*DDn*DDn);
        wtrans_split<<<blocks,256>>>(Wv,  wthi + 3*DDn*DDn, wtlo + 3*DDn*DDn);
        wtrans_split<<<blocks,256>>>(Wo1, wthi + 4*DDn*DDn, wtlo + 4*DDn*DDn);
        wtrans_split<<<blocks,256>>>(Wo2, wthi + 5*DDn*DDn, wtlo + 5*DDn*DDn);
    }
    // 3. h = p @ W1 + b1
    gemm(phi, plo, wthi + 0*DDn*DDn, wtlo + 0*DDn*DDn, b1,
         nullptr, hhi, hlo, ROWS, DDn, DDn, DDn, DDn, DDn, 0,0,0, 1,1, 1.f, 0, 0);
    // 4. Q = h[:,0] @ Wq + bq (remap)
    gemm(hhi, hlo, wthi + 1*DDn*DDn, wtlo + 1*DDn*DDn, bq,
         nullptr, qhi, qlo, QROWS, DDn, DDn, DDn, DDn, DDn, 0,0,0, 1,1, 1.f, 0, 1);
    // 5. K = h @ Wk + bk
    gemm(hhi, hlo, wthi + 2*DDn*DDn, wtlo + 2*DDn*DDn, bk,
         nullptr, khi, klo, ROWS, DDn, DDn, DDn, DDn, DDn, 0,0,0, 1,1, 1.f, 0, 0);
    // 6. V = h @ Wv + bv (fp32)
    gemm(hhi, hlo, wthi + 3*DDn*DDn, wtlo + 3*DDn*DDn, bv,
         v, nullptr, nullptr, ROWS, DDn, DDn, DDn, DDn, DDn, 0,0,0, 1,1, 1.f, 0, 0);
    // 7. V transpose -> Vt [z][768][256]
    {
        dim3 g(DDn/32, KPAD/32, NBat), b(32, 8);
        vtrans_split<<<g, b>>>(v, vthi, vtlo);
    }
    // 8. scores = scale * Q @ K^T (batched)
    {
        float scale = 1.f / sqrtf((float)DDn);
        gemm(qhi, qlo, khi, klo, nullptr, sc, nullptr, nullptr,
             SSn, SSn, DDn, DDn, DDn, SSn,
             (long long)SSn*DDn, (long long)SSn*DDn, (long long)SSn*SSn,
             NPIC, NBat, scale, 0, 0);
    }
    // 9. softmax -> attn hi/lo (padded 256)
    {
        int nrows = NBat * SSn;
        softmax_split<<<(nrows + 7)/8, 8*32>>>(sc, athi, atlo);
    }
    // 10. wv = attn @ V (B = Vt)
    gemm(athi, atlo, vthi, vtlo, nullptr, nullptr, wvhi, wvlo,
         SSn, DDn, KPAD, KPAD, KPAD, DDn,
         (long long)SSn*KPAD, (long long)DDn*KPAD, (long long)SSn*DDn,
         1, NBat, 1.f, 0, 0);
    // 11. t = relu(wv @ Wo1 + bo1)
    gemm(wvhi, wvlo, wthi + 4*DDn*DDn, wtlo + 4*DDn*DDn, bo1,
         nullptr, thi, tlo, ROWS, DDn, DDn, DDn, DDn, DDn, 0,0,0, 1,1, 1.f, 1, 0);
    // 12. out = t @ Wo2 + bo2
    gemm(thi, tlo, wthi + 5*DDn*DDn, wtlo + 5*DDn*DDn, bo2,
         out, nullptr, nullptr, ROWS, DDn, DDn, DDn, DDn, DDn, 0,0,0, 1,1, 1.f, 0, 0);
}

// round 6
// speedup vs baseline: 4.8804x; 1.9511x over previous
#include <cuda_runtime.h>
#include <cuda_fp16.h>
#include <stdint.h>
#include <math.h>

// ================= problem constants =================
#define Bsz   32
#define NPIC  4
#define CCH   3
#define Him   224
#define Wim   224
#define PPs   16
#define HPn   14
#define SSn   196
#define DDn   768
#define ROWS  (Bsz*NPIC*SSn)   // 25088
#define QROWS (Bsz*SSn)        // 6272
#define NBat  (Bsz*NPIC)       // 128
#define KPAD  256

// ================= device scratch =================
__device__ __align__(1024) __half g_p  [ROWS*DDn];
__device__ __align__(1024) __half g_wt [6*DDn*DDn];
__device__ __align__(1024) __half g_h  [ROWS*DDn];
__device__ __align__(1024) __half g_q  [QROWS*DDn];
__device__ __align__(1024) __half g_k  [ROWS*DDn];
__device__ __align__(1024) __half g_v  [ROWS*DDn];
__device__ __align__(1024) __half g_vt [NBat*DDn*KPAD];
__device__ __align__(1024) float  g_sc [NBat*SSn*SSn];
__device__ __align__(1024) __half g_at [NBat*SSn*KPAD];
__device__ __align__(1024) __half g_wv [ROWS*DDn];
__device__ __align__(1024) __half g_t  [ROWS*DDn];

// ================= helpers =================
__device__ __forceinline__ uint32_t smem_u32(const void* p){
    uint32_t a;
    asm("{ .reg .u64 t; cvta.to.shared.u64 t, %1; cvt.u32.u64 %0, t; }" : "=r"(a) : "l"(p));
    return a;
}
#define SWZ128(o) ((o) ^ (((o) >> 3) & 0x70))

__device__ __forceinline__ void cp16(uint32_t dst, const void* src, int nbytes){
    asm volatile("cp.async.cg.shared.global [%0], [%1], 16, %2;"
                 :: "r"(dst), "l"(src), "r"(nbytes) : "memory");
}
__device__ __forceinline__ void cp_commit(){ asm volatile("cp.async.commit_group;" ::: "memory"); }
__device__ __forceinline__ void cp_wait1(){  asm volatile("cp.async.wait_group 1;" ::: "memory"); }

__device__ __forceinline__ void ldsm4(uint32_t& r0,uint32_t& r1,uint32_t& r2,uint32_t& r3,uint32_t a){
    asm volatile("ldmatrix.sync.aligned.m8n8.x4.shared.b16 {%0,%1,%2,%3}, [%4];"
        : "=r"(r0),"=r"(r1),"=r"(r2),"=r"(r3) : "r"(a));
}
__device__ __forceinline__ void mma16816(float* c, const uint32_t* a, const uint32_t* b){
    asm volatile("mma.sync.aligned.m16n8k16.row.col.f32.f16.f16.f32 "
        "{%0,%1,%2,%3}, {%4,%5,%6,%7}, {%8,%9}, {%0,%1,%2,%3};"
        : "+f"(c[0]),"+f"(c[1]),"+f"(c[2]),"+f"(c[3])
        : "r"(a[0]),"r"(a[1]),"r"(a[2]),"r"(a[3]), "r"(b[0]),"r"(b[1]));
}

// ================= patchify -> fp16 =================
__global__ void patchify_h(const float* __restrict__ x, __half* __restrict__ p)
{
    long long idx = (long long)blockIdx.x * blockDim.x + threadIdx.x;
    long long total = (long long)ROWS * DDn;
    if (idx >= total) return;
    int d    = (int)(idx % DDn);
    int rest = (int)(idx / DDn);
    int s    = rest % SSn;
    int pic  = rest / SSn;
    int c  = d >> 8;
    int rm = d & 255;
    int ph = rm >> 4;
    int pw = rm & 15;
    int i = s / HPn, j = s % HPn;
    long long src = (((long long)pic * CCH + c) * Him + (i*PPs + ph)) * Wim + (j*PPs + pw);
    p[idx] = __float2half(x[src]);
}

// ================= weight transpose -> fp16 =================
__global__ void wtrans_h(const float* __restrict__ W, __half* __restrict__ wt)
{
    int idx = blockIdx.x * blockDim.x + threadIdx.x;
    if (idx >= DDn*DDn) return;
    int n = idx / DDn, k = idx % DDn;
    wt[idx] = __float2half(W[k*DDn + n]);
}

// ================= V transpose (fp16 -> fp16, pad 256) =================
__global__ void vtrans_h(const __half* __restrict__ V, __half* __restrict__ vt)
{
    __shared__ __half tile[32][33];
    int z  = blockIdx.z;
    int d0 = blockIdx.x * 32;
    int s0 = blockIdx.y * 32;
    int tx = threadIdx.x, ty = threadIdx.y;
    for (int sy = ty; sy < 32; sy += 8) {
        int s = s0 + sy, d = d0 + tx;
        tile[sy][tx] = (s < SSn) ? V[((long long)z*SSn + s)*DDn + d] : __float2half(0.f);
    }
    __syncthreads();
    for (int dy = ty; dy < 32; dy += 8) {
        int d = d0 + dy, s = s0 + tx;
        vt[((long long)z*DDn + d)*KPAD + s] = tile[tx][dy];
    }
}

// ================= softmax (fp32 in, fp16 out padded 256) =================
__global__ void softmax_h(const float* __restrict__ S, __half* __restrict__ a)
{
    int warp = (blockIdx.x * blockDim.x + threadIdx.x) >> 5;
    int lane = threadIdx.x & 31;
    if (warp >= NBat*SSn) return;
    const float* row = S + (long long)warp * SSn;
    float v[7];
    float m = -INFINITY;
#pragma unroll
    for (int i = 0; i < 7; i++) {
        int c = lane + i*32;
        v[i] = (c < SSn) ? row[c] : -INFINITY;
        m = fmaxf(m, v[i]);
    }
#pragma unroll
    for (int o = 16; o > 0; o >>= 1) m = fmaxf(m, __shfl_xor_sync(0xffffffffu, m, o));
    float sum = 0.f;
#pragma unroll
    for (int i = 0; i < 7; i++) {
        int c = lane + i*32;
        if (c < SSn) { v[i] = __expf(v[i] - m); sum += v[i]; } else v[i] = 0.f;
    }
#pragma unroll
    for (int o = 16; o > 0; o >>= 1) sum += __shfl_xor_sync(0xffffffffu, sum, o);
    float inv = 1.f / sum;
    __half* oh = a + (long long)warp * KPAD;
#pragma unroll
    for (int i = 0; i < 8; i++) {
        int c = lane + i*32;
        float val = (i < 7 && c < SSn) ? v[i] * inv : 0.f;
        oh[c] = __float2half(val);
    }
}

// ================= mma.sync fp16 GEMM (128x256 tile) =================
#define BMt 128
#define BNt 256
#define BKt 64
#define NTHR 256
#define TILEA 16384                    // 128 rows * 128B
#define TILEB 32768                    // 256 rows * 128B
#define STGSZ (TILEA + TILEB)          // 48KB per stage
#define DSM   (2*STGSZ + 1024)

__global__ void __launch_bounds__(NTHR)
mm_gemm(const __half* __restrict__ A, const __half* __restrict__ B,
        const float* __restrict__ bias,
        float* __restrict__ Cf, __half* __restrict__ Ch,
        int M, int Nvalid, int K, int ldA, int ldB, int ldC,
        long long sA, long long sB, long long sC, int zdivA,
        float alpha, int relu, int remapA)
{
    extern __shared__ char dsm[];
    uint32_t dyn  = smem_u32(dsm);
    uint32_t base = (dyn + 1023u) & ~1023u;
    const uint32_t stg[2] = { base, base + STGSZ };

    const int t = threadIdx.x, lane = t & 31, w = t >> 5;
    const int wm = w & 1, wn = w >> 1;          // 2 x 4 warps; warp tile 64x64
    const int z = blockIdx.z;
    const int m0 = blockIdx.y * BMt;
    const int n0 = blockIdx.x * BNt;

    const __half* Az = A + (long long)(z / zdivA) * sA;
    const __half* Bz = B + (long long)z * sB;
    float* Cfz = Cf ? Cf + (long long)z * sC : nullptr;
    __half* Chz = Ch ? Ch + (long long)z * sC : nullptr;

    float acc[4][8][4];
#pragma unroll
    for (int a = 0; a < 4; a++)
#pragma unroll
        for (int b = 0; b < 8; b++)
#pragma unroll
            for (int c = 0; c < 4; c++) acc[a][b][c] = 0.f;

    const int ITERS = K / BKt;

#define LOAD_STAGE(ITN, BUF)                                                         \
    {                                                                                \
        int k0 = (ITN) * BKt;                                                        \
        _Pragma("unroll")                                                            \
        for (int j = 0; j < 4; j++) {                                                \
            int flat = t + j*256;                                                    \
            int row = flat >> 3, cc = flat & 7;                                      \
            uint32_t so = SWZ128((uint32_t)(row*128 + cc*16));                       \
            int gr = m0 + row;                                                       \
            int ok = gr < M;                                                         \
            long long pr = 0;                                                        \
            if (ok) pr = remapA ? (long long)gr + (gr/SSn)*(NPIC*SSn - SSn)          \
                                : (long long)gr;                                     \
            cp16(stg[BUF] + so, Az + pr*ldA + k0 + cc*8, ok ? 16 : 0);               \
        }                                                                            \
        _Pragma("unroll")                                                            \
        for (int j = 0; j < 8; j++) {                                                \
            int flat = t + j*256;                                                    \
            int row = flat >> 3, cc = flat & 7;                                      \
            uint32_t so = SWZ128((uint32_t)(row*128 + cc*16));                       \
            int gn = n0 + row;                                                       \
            int okb = gn < Nvalid;                                                   \
            long long pn = okb ? gn : 0;                                             \
            cp16(stg[BUF] + TILEA + so, Bz + pn*ldB + k0 + cc*8, okb ? 16 : 0);      \
        }                                                                            \
    }

    LOAD_STAGE(0, 0);
    cp_commit();

    const int rl = lane & 15, hh = lane >> 4;

    for (int itn = 0; itn < ITERS; itn++) {
        int buf = itn & 1;
        if (itn + 1 < ITERS) LOAD_STAGE(itn + 1, buf ^ 1);
        cp_commit();
        cp_wait1();
        __syncthreads();

        uint32_t sA_ = stg[buf], sB_ = stg[buf] + TILEA;
#pragma unroll
        for (int ks = 0; ks < 4; ks++) {
            int c = ks*2 + hh;
            uint32_t af[4][4], bf[8][2];
#pragma unroll
            for (int mt = 0; mt < 4; mt++) {
                int row = wm*64 + mt*16 + rl;
                uint32_t so = SWZ128((uint32_t)(row*128 + c*16));
                ldsm4(af[mt][0], af[mt][1], af[mt][2], af[mt][3], sA_ + so);
            }
#pragma unroll
            for (int bt = 0; bt < 4; bt++) {
                int row = wn*64 + bt*16 + rl;
                uint32_t so = SWZ128((uint32_t)(row*128 + c*16));
                uint32_t r0, r1, r2, r3;
                ldsm4(r0, r1, r2, r3, sB_ + so);
                bf[bt*2][0]   = r0;  bf[bt*2][1]   = r2;
                bf[bt*2+1][0] = r1;  bf[bt*2+1][1] = r3;
            }
#pragma unroll
            for (int mt = 0; mt < 4; mt++)
#pragma unroll
                for (int nt = 0; nt < 8; nt++)
                    mma16816(acc[mt][nt], af[mt], bf[nt]);
        }
        __syncthreads();
    }

    // ---- epilogue ----
    const int r0l = lane >> 2, cl = (lane & 3) * 2;
#pragma unroll
    for (int mt = 0; mt < 4; mt++) {
#pragma unroll
        for (int nt = 0; nt < 8; nt++) {
            int gc = n0 + wn*64 + nt*8 + cl;
#pragma unroll
            for (int half = 0; half < 2; half++) {
                int gr = m0 + wm*64 + mt*16 + r0l + half*8;
                if (gr >= M) continue;
                float v0 = acc[mt][nt][half*2 + 0] * alpha;
                float v1 = acc[mt][nt][half*2 + 1] * alpha;
                if (bias) { v0 += __ldg(bias + gc); v1 += __ldg(bias + gc + 1); }
                if (relu) { v0 = fmaxf(v0, 0.f); v1 = fmaxf(v1, 0.f); }
                long long o = (long long)gr * ldC + gc;
                if (gc < Nvalid) {
                    if (Cfz) Cfz[o] = v0;
                    if (Chz) Chz[o] = __float2half(v0);
                }
                if (gc + 1 < Nvalid) {
                    if (Cfz) Cfz[o+1] = v1;
                    if (Chz) Chz[o+1] = __float2half(v1);
                }
            }
        }
    }
}

// ================= host side =================
static void gemm(const __half* A, const __half* B, const float* bias,
                 float* Cf, __half* Ch,
                 int M, int Nvalid, int K, int ldA, int ldB, int ldC,
                 long long sA, long long sB, long long sC, int zdivA, int nz,
                 float alpha, int relu, int remapA)
{
    dim3 g((Nvalid + BNt - 1)/BNt, (M + BMt - 1)/BMt, nz);
    mm_gemm<<<g, NTHR, DSM>>>(A, B, bias, Cf, Ch,
                              M, Nvalid, K, ldA, ldB, ldC, sA, sB, sC,
                              zdivA, alpha, relu, remapA);
}

extern "C" void kernel_launch(void* const* d_in, const int* in_sizes, int n_in,
                              void* d_out, int out_size)
{
    const float* x   = (const float*)d_in[0];
    const float* W1  = (const float*)d_in[1];
    const float* b1  = (const float*)d_in[2];
    const float* Wq  = (const float*)d_in[3];
    const float* bq  = (const float*)d_in[4];
    const float* Wk  = (const float*)d_in[5];
    const float* bk  = (const float*)d_in[6];
    const float* Wv  = (const float*)d_in[7];
    const float* bv  = (const float*)d_in[8];
    const float* Wo1 = (const float*)d_in[9];
    const float* bo1 = (const float*)d_in[10];
    const float* Wo2 = (const float*)d_in[11];
    const float* bo2 = (const float*)d_in[12];
    float* out = (float*)d_out;

    cudaFuncSetAttribute(mm_gemm, cudaFuncAttributeMaxDynamicSharedMemorySize, DSM);

    __half *p,*wt,*h,*q,*k,*v,*vt,*at,*wv,*tb;
    float *sc;
    cudaGetSymbolAddress((void**)&p,  g_p);
    cudaGetSymbolAddress((void**)&wt, g_wt);
    cudaGetSymbolAddress((void**)&h,  g_h);
    cudaGetSymbolAddress((void**)&q,  g_q);
    cudaGetSymbolAddress((void**)&k,  g_k);
    cudaGetSymbolAddress((void**)&v,  g_v);
    cudaGetSymbolAddress((void**)&vt, g_vt);
    cudaGetSymbolAddress((void**)&sc, g_sc);
    cudaGetSymbolAddress((void**)&at, g_at);
    cudaGetSymbolAddress((void**)&wv, g_wv);
    cudaGetSymbolAddress((void**)&tb, g_t);

    // 1. patchify
    {
        long long total = (long long)ROWS * DDn;
        patchify_h<<<(unsigned)((total + 255)/256), 256>>>(x, p);
    }
    // 2. weight transpose
    {
        int nthr = DDn*DDn, blocks = (nthr + 255)/256;
        wtrans_h<<<blocks,256>>>(W1,  wt + 0*DDn*DDn);
        wtrans_h<<<blocks,256>>>(Wq,  wt + 1*DDn*DDn);
        wtrans_h<<<blocks,256>>>(Wk,  wt + 2*DDn*DDn);
        wtrans_h<<<blocks,256>>>(Wv,  wt + 3*DDn*DDn);
        wtrans_h<<<blocks,256>>>(Wo1, wt + 4*DDn*DDn);
        wtrans_h<<<blocks,256>>>(Wo2, wt + 5*DDn*DDn);
    }
    // 3. h = p @ W1 + b1
    gemm(p, wt + 0*DDn*DDn, b1, nullptr, h,
         ROWS, DDn, DDn, DDn, DDn, DDn, 0,0,0, 1,1, 1.f, 0, 0);
    // 4. Q = h[:,0] @ Wq + bq (remap)
    gemm(h, wt + 1*DDn*DDn, bq, nullptr, q,
         QROWS, DDn, DDn, DDn, DDn, DDn, 0,0,0, 1,1, 1.f, 0, 1);
    // 5. K = h @ Wk + bk
    gemm(h, wt + 2*DDn*DDn, bk, nullptr, k,
         ROWS, DDn, DDn, DDn, DDn, DDn, 0,0,0, 1,1, 1.f, 0, 0);
    // 6. V = h @ Wv + bv
    gemm(h, wt + 3*DDn*DDn, bv, nullptr, v,
         ROWS, DDn, DDn, DDn, DDn, DDn, 0,0,0, 1,1, 1.f, 0, 0);
    // 7. V transpose -> Vt [z][768][256]
    {
        dim3 g(DDn/32, KPAD/32, NBat), b(32, 8);
        vtrans_h<<<g, b>>>(v, vt);
    }
    // 8. scores = scale * Q @ K^T (batched)
    {
        float scale = 1.f / sqrtf((float)DDn);
        gemm(q, k, nullptr, sc, nullptr,
             SSn, SSn, DDn, DDn, DDn, SSn,
             (long long)SSn*DDn, (long long)SSn*DDn, (long long)SSn*SSn,
             NPIC, NBat, scale, 0, 0);
    }
    // 9. softmax -> attn fp16 (padded 256)
    {
        int nrows = NBat * SSn;
        softmax_h<<<(nrows + 7)/8, 8*32>>>(sc, at);
    }
    // 10. wv = attn @ V (B = Vt)
    gemm(at, vt, nullptr, nullptr, wv,
         SSn, DDn, KPAD, KPAD, KPAD, DDn,
         (long long)SSn*KPAD, (long long)DDn*KPAD, (long long)SSn*DDn,
         1, NBat, 1.f, 0, 0);
    // 11. t = relu(wv @ Wo1 + bo1)
    gemm(wv, wt + 4*DDn*DDn, bo1, nullptr, tb,
         ROWS, DDn, DDn, DDn, DDn, DDn, 0,0,0, 1,1, 1.f, 1, 0);
    // 12. out = t @ Wo2 + bo2
    gemm(tb, wt + 5*DDn*DDn, bo2, out, nullptr,
         ROWS, DDn, DDn, DDn, DDn, DDn, 0,0,0, 1,1, 1.f, 0, 0);
}

// round 9
// speedup vs baseline: 5.0198x; 1.0286x over previous
#include <cuda_runtime.h>
#include <cuda_fp16.h>
#include <stdint.h>
#include <math.h>

// ================= problem constants =================
#define Bsz   32
#define NPIC  4
#define CCH   3
#define Him   224
#define Wim   224
#define PPs   16
#define HPn   14
#define SSn   196
#define DDn   768
#define ROWS  (Bsz*NPIC*SSn)   // 25088
#define QROWS (Bsz*SSn)        // 6272
#define NBat  (Bsz*NPIC)       // 128
#define KPAD  256

// ================= device scratch =================
__device__ __align__(1024) __half g_p  [ROWS*DDn];
__device__ __align__(1024) __half g_wt [6*DDn*DDn];
__device__ __align__(1024) __half g_h  [ROWS*DDn];
__device__ __align__(1024) __half g_q  [QROWS*DDn];
__device__ __align__(1024) __half g_k  [ROWS*DDn];
__device__ __align__(1024) __half g_v  [ROWS*DDn];
__device__ __align__(1024) __half g_vt [NBat*DDn*KPAD];
__device__ __align__(1024) __half g_at [NBat*SSn*KPAD];
__device__ __align__(1024) __half g_wv [ROWS*DDn];
__device__ __align__(1024) __half g_t  [ROWS*DDn];

// ================= helpers =================
__device__ __forceinline__ uint32_t smem_u32(const void* p){
    uint32_t a;
    asm("{ .reg .u64 t; cvta.to.shared.u64 t, %1; cvt.u32.u64 %0, t; }" : "=r"(a) : "l"(p));
    return a;
}
#define SWZ128(o) ((o) ^ (((o) >> 3) & 0x70))

__device__ __forceinline__ void cp16(uint32_t dst, const void* src, int nbytes){
    asm volatile("cp.async.cg.shared.global [%0], [%1], 16, %2;"
                 :: "r"(dst), "l"(src), "r"(nbytes) : "memory");
}
__device__ __forceinline__ void cp_commit(){ asm volatile("cp.async.commit_group;" ::: "memory"); }
__device__ __forceinline__ void cp_wait2(){  asm volatile("cp.async.wait_group 2;" ::: "memory"); }

__device__ __forceinline__ void ldsm4(uint32_t& r0,uint32_t& r1,uint32_t& r2,uint32_t& r3,uint32_t a){
    asm volatile("ldmatrix.sync.aligned.m8n8.x4.shared.b16 {%0,%1,%2,%3}, [%4];"
        : "=r"(r0),"=r"(r1),"=r"(r2),"=r"(r3) : "r"(a));
}
__device__ __forceinline__ void mma16816(float* c, const uint32_t* a, const uint32_t* b){
    asm volatile("mma.sync.aligned.m16n8k16.row.col.f32.f16.f16.f32 "
        "{%0,%1,%2,%3}, {%4,%5,%6,%7}, {%8,%9}, {%0,%1,%2,%3};"
        : "+f"(c[0]),"+f"(c[1]),"+f"(c[2]),"+f"(c[3])
        : "r"(a[0]),"r"(a[1]),"r"(a[2]),"r"(a[3]), "r"(b[0]),"r"(b[1]));
}

// ================= patchify -> fp16 =================
__global__ void patchify_h(const float* __restrict__ x, __half* __restrict__ p)
{
    long long idx = (long long)blockIdx.x * blockDim.x + threadIdx.x;
    long long total = (long long)ROWS * DDn;
    if (idx >= total) return;
    int d    = (int)(idx % DDn);
    int rest = (int)(idx / DDn);
    int s    = rest % SSn;
    int pic  = rest / SSn;
    int c  = d >> 8;
    int rm = d & 255;
    int ph = rm >> 4;
    int pw = rm & 15;
    int i = s / HPn, j = s % HPn;
    long long src = (((long long)pic * CCH + c) * Him + (i*PPs + ph)) * Wim + (j*PPs + pw);
    p[idx] = __float2half(x[src]);
}

// ================= weight transpose -> fp16 =================
__global__ void wtrans_h(const float* __restrict__ W, __half* __restrict__ wt)
{
    int idx = blockIdx.x * blockDim.x + threadIdx.x;
    if (idx >= DDn*DDn) return;
    int n = idx / DDn, k = idx % DDn;
    wt[idx] = __float2half(W[k*DDn + n]);
}

// ================= V transpose (fp16, pad 256) =================
__global__ void vtrans_h(const __half* __restrict__ V, __half* __restrict__ vt)
{
    __shared__ __half tile[32][33];
    int z  = blockIdx.z;
    int d0 = blockIdx.x * 32;
    int s0 = blockIdx.y * 32;
    int tx = threadIdx.x, ty = threadIdx.y;
    for (int sy = ty; sy < 32; sy += 8) {
        int s = s0 + sy, d = d0 + tx;
        tile[sy][tx] = (s < SSn) ? V[((long long)z*SSn + s)*DDn + d] : __float2half(0.f);
    }
    __syncthreads();
    for (int dy = ty; dy < 32; dy += 8) {
        int d = d0 + dy, s = s0 + tx;
        vt[((long long)z*DDn + d)*KPAD + s] = tile[tx][dy];
    }
}

// ================= mma.sync fp16 GEMM (128x256 tile, 3-stage pipeline) =====
#define BMt 128
#define BNt 256
#define BKt 64
#define NTHR 256
#define TILEA 16384                    // 128 rows * 128B
#define TILEB 32768                    // 256 rows * 128B
#define STGSZ (TILEA + TILEB)          // 48KB per stage
#define DSM   (3*STGSZ + 1024)

__global__ void __launch_bounds__(NTHR)
mm_gemm(const __half* __restrict__ A, const __half* __restrict__ B,
        const float* __restrict__ bias,
        float* __restrict__ Cf, __half* __restrict__ Ch, __half* __restrict__ Smx,
        int M, int Nvalid, int K, int ldA, int ldB, int ldC,
        long long sA, long long sB, long long sC, int zdivA,
        float alpha, int relu, int remapA)
{
    extern __shared__ char dsm[];
    uint32_t dyn  = smem_u32(dsm);
    uint32_t base = (dyn + 1023u) & ~1023u;
    const uint32_t stg[3] = { base, base + STGSZ, base + 2*STGSZ };

    const int t = threadIdx.x, lane = t & 31, w = t >> 5;
    const int wm = w & 1, wn = w >> 1;          // 2 x 4 warps; warp tile 64x64
    const int z = blockIdx.z;
    const int m0 = blockIdx.y * BMt;
    const int n0 = blockIdx.x * BNt;

    const __half* Az = A + (long long)(z / zdivA) * sA;
    const __half* Bz = B + (long long)z * sB;
    float* Cfz = Cf ? Cf + (long long)z * sC : nullptr;
    __half* Chz = Ch ? Ch + (long long)z * sC : nullptr;
    __half* Smxz = Smx ? Smx + (long long)z * sC : nullptr;

    float acc[4][8][4];
#pragma unroll
    for (int a = 0; a < 4; a++)
#pragma unroll
        for (int b = 0; b < 8; b++)
#pragma unroll
            for (int c = 0; c < 4; c++) acc[a][b][c] = 0.f;

    const int ITERS = K / BKt;

#define LOAD_STAGE(ITN, BUF)                                                         \
    {                                                                                \
        int k0 = (ITN) * BKt;                                                        \
        _Pragma("unroll")                                                            \
        for (int j = 0; j < 4; j++) {                                                \
            int flat = t + j*256;                                                    \
            int row = flat >> 3, cc = flat & 7;                                      \
            uint32_t so = SWZ128((uint32_t)(row*128 + cc*16));                       \
            int gr = m0 + row;                                                       \
            int ok = gr < M;                                                         \
            long long pr = 0;                                                        \
            if (ok) pr = remapA ? (long long)gr + (gr/SSn)*(NPIC*SSn - SSn)          \
                                : (long long)gr;                                     \
            cp16(stg[BUF] + so, Az + pr*ldA + k0 + cc*8, ok ? 16 : 0);               \
        }                                                                            \
        _Pragma("unroll")                                                            \
        for (int j = 0; j < 8; j++) {                                                \
            int flat = t + j*256;                                                    \
            int row = flat >> 3, cc = flat & 7;                                      \
            uint32_t so = SWZ128((uint32_t)(row*128 + cc*16));                       \
            int gn = n0 + row;                                                       \
            int okb = gn < Nvalid;                                                   \
            long long pn = okb ? gn : 0;                                             \
            cp16(stg[BUF] + TILEA + so, Bz + pn*ldB + k0 + cc*8, okb ? 16 : 0);      \
        }                                                                            \
    }

    LOAD_STAGE(0, 0); cp_commit();
    LOAD_STAGE(1, 1); cp_commit();

    const int rl = lane & 15, hh = lane >> 4;

    for (int itn = 0; itn < ITERS; itn++) {
        int buf = itn % 3;
        // prefetch 2 ahead (empty commit keeps group count constant)
        if (itn + 2 < ITERS) { int nb = (itn + 2) % 3; LOAD_STAGE(itn + 2, nb); }
        cp_commit();
        cp_wait2();
        __syncthreads();

        uint32_t sA_ = stg[buf], sB_ = stg[buf] + TILEA;
#pragma unroll
        for (int ks = 0; ks < 4; ks++) {
            int c = ks*2 + hh;
            uint32_t af[4][4], bf[8][2];
#pragma unroll
            for (int mt = 0; mt < 4; mt++) {
                int row = wm*64 + mt*16 + rl;
                uint32_t so = SWZ128((uint32_t)(row*128 + c*16));
                ldsm4(af[mt][0], af[mt][1], af[mt][2], af[mt][3], sA_ + so);
            }
#pragma unroll
            for (int bt = 0; bt < 4; bt++) {
                int row = wn*64 + bt*16 + rl;
                uint32_t so = SWZ128((uint32_t)(row*128 + c*16));
                uint32_t r0, r1, r2, r3;
                ldsm4(r0, r1, r2, r3, sB_ + so);
                bf[bt*2][0]   = r0;  bf[bt*2][1]   = r2;
                bf[bt*2+1][0] = r1;  bf[bt*2+1][1] = r3;
            }
#pragma unroll
            for (int mt = 0; mt < 4; mt++)
#pragma unroll
                for (int nt = 0; nt < 8; nt++)
                    mma16816(acc[mt][nt], af[mt], bf[nt]);
        }
    }

    const int r0l = lane >> 2, cl = (lane & 3) * 2;

    if (Smx) {
        // ---- fused softmax epilogue (CTA holds full rows; Nvalid=196) ----
        __half* stage = (__half*)(dsm + (base - dyn));   // 128 x 256 fp16 = 64KB
        __syncthreads();   // all warps done reading smem tiles
#pragma unroll
        for (int mt = 0; mt < 4; mt++)
#pragma unroll
            for (int nt = 0; nt < 8; nt++) {
                int col = wn*64 + nt*8 + cl;
#pragma unroll
                for (int half = 0; half < 2; half++) {
                    int r = wm*64 + mt*16 + r0l + half*8;
                    stage[r*256 + col]     = __float2half(acc[mt][nt][half*2 + 0] * alpha);
                    stage[r*256 + col + 1] = __float2half(acc[mt][nt][half*2 + 1] * alpha);
                }
            }
        __syncthreads();
        // warp w handles rows w*16 .. w*16+15
        for (int rr = 0; rr < 16; rr++) {
            int r = w*16 + rr;
            int gr = m0 + r;
            if (gr >= M) continue;
            float v[7];
            float mx = -INFINITY;
#pragma unroll
            for (int i = 0; i < 7; i++) {
                int c = lane + i*32;
                v[i] = (c < SSn) ? __half2float(stage[r*256 + c]) : -INFINITY;
                mx = fmaxf(mx, v[i]);
            }
#pragma unroll
            for (int o = 16; o > 0; o >>= 1) mx = fmaxf(mx, __shfl_xor_sync(0xffffffffu, mx, o));
            float sum = 0.f;
#pragma unroll
            for (int i = 0; i < 7; i++) {
                int c = lane + i*32;
                if (c < SSn) { v[i] = __expf(v[i] - mx); sum += v[i]; } else v[i] = 0.f;
            }
#pragma unroll
            for (int o = 16; o > 0; o >>= 1) sum += __shfl_xor_sync(0xffffffffu, sum, o);
            float inv = 1.f / sum;
            __half* orow = Smxz + (long long)gr * KPAD;
#pragma unroll
            for (int i = 0; i < 8; i++) {
                int c = lane + i*32;
                float val = (i < 7 && c < SSn) ? v[i] * inv : 0.f;
                orow[c] = __float2half(val);
            }
        }
        return;
    }

    // ---- normal epilogue ----
#pragma unroll
    for (int mt = 0; mt < 4; mt++) {
#pragma unroll
        for (int nt = 0; nt < 8; nt++) {
            int gc = n0 + wn*64 + nt*8 + cl;
#pragma unroll
            for (int half = 0; half < 2; half++) {
                int gr = m0 + wm*64 + mt*16 + r0l + half*8;
                if (gr >= M) continue;
                float v0 = acc[mt][nt][half*2 + 0] * alpha;
                float v1 = acc[mt][nt][half*2 + 1] * alpha;
                if (bias) { v0 += __ldg(bias + gc); v1 += __ldg(bias + gc + 1); }
                if (relu) { v0 = fmaxf(v0, 0.f); v1 = fmaxf(v1, 0.f); }
                long long o = (long long)gr * ldC + gc;
                if (gc < Nvalid) {
                    if (Cfz) Cfz[o] = v0;
                    if (Chz) Chz[o] = __float2half(v0);
                }
                if (gc + 1 < Nvalid) {
                    if (Cfz) Cfz[o+1] = v1;
                    if (Chz) Chz[o+1] = __float2half(v1);
                }
            }
        }
    }
}

// ================= host side =================
static void gemm(const __half* A, const __half* B, const float* bias,
                 float* Cf, __half* Ch, __half* Smx,
                 int M, int Nvalid, int K, int ldA, int ldB, int ldC,
                 long long sA, long long sB, long long sC, int zdivA, int nz,
                 float alpha, int relu, int remapA)
{
    dim3 g((Nvalid + BNt - 1)/BNt, (M + BMt - 1)/BMt, nz);
    mm_gemm<<<g, NTHR, DSM>>>(A, B, bias, Cf, Ch, Smx,
                              M, Nvalid, K, ldA, ldB, ldC, sA, sB, sC,
                              zdivA, alpha, relu, remapA);
}

extern "C" void kernel_launch(void* const* d_in, const int* in_sizes, int n_in,
                              void* d_out, int out_size)
{
    const float* x   = (const float*)d_in[0];
    const float* W1  = (const float*)d_in[1];
    const float* b1  = (const float*)d_in[2];
    const float* Wq  = (const float*)d_in[3];
    const float* bq  = (const float*)d_in[4];
    const float* Wk  = (const float*)d_in[5];
    const float* bk  = (const float*)d_in[6];
    const float* Wv  = (const float*)d_in[7];
    const float* bv  = (const float*)d_in[8];
    const float* Wo1 = (const float*)d_in[9];
    const float* bo1 = (const float*)d_in[10];
    const float* Wo2 = (const float*)d_in[11];
    const float* bo2 = (const float*)d_in[12];
    float* out = (float*)d_out;

    cudaFuncSetAttribute(mm_gemm, cudaFuncAttributeMaxDynamicSharedMemorySize, DSM);

    __half *p,*wt,*h,*q,*k,*v,*vt,*at,*wv,*tb;
    cudaGetSymbolAddress((void**)&p,  g_p);
    cudaGetSymbolAddress((void**)&wt, g_wt);
    cudaGetSymbolAddress((void**)&h,  g_h);
    cudaGetSymbolAddress((void**)&q,  g_q);
    cudaGetSymbolAddress((void**)&k,  g_k);
    cudaGetSymbolAddress((void**)&v,  g_v);
    cudaGetSymbolAddress((void**)&vt, g_vt);
    cudaGetSymbolAddress((void**)&at, g_at);
    cudaGetSymbolAddress((void**)&wv, g_wv);
    cudaGetSymbolAddress((void**)&tb, g_t);

    // 1. patchify
    {
        long long total = (long long)ROWS * DDn;
        patchify_h<<<(unsigned)((total + 255)/256), 256>>>(x, p);
    }
    // 2. weight transpose
    {
        int nthr = DDn*DDn, blocks = (nthr + 255)/256;
        wtrans_h<<<blocks,256>>>(W1,  wt + 0*DDn*DDn);
        wtrans_h<<<blocks,256>>>(Wq,  wt + 1*DDn*DDn);
        wtrans_h<<<blocks,256>>>(Wk,  wt + 2*DDn*DDn);
        wtrans_h<<<blocks,256>>>(Wv,  wt + 3*DDn*DDn);
        wtrans_h<<<blocks,256>>>(Wo1, wt + 4*DDn*DDn);
        wtrans_h<<<blocks,256>>>(Wo2, wt + 5*DDn*DDn);
    }
    // 3. h = p @ W1 + b1
    gemm(p, wt + 0*DDn*DDn, b1, nullptr, h, nullptr,
         ROWS, DDn, DDn, DDn, DDn, DDn, 0,0,0, 1,1, 1.f, 0, 0);
    // 4. Q = h[:,0] @ Wq + bq (remap)
    gemm(h, wt + 1*DDn*DDn, bq, nullptr, q, nullptr,
         QROWS, DDn, DDn, DDn, DDn, DDn, 0,0,0, 1,1, 1.f, 0, 1);
    // 5. K = h @ Wk + bk
    gemm(h, wt + 2*DDn*DDn, bk, nullptr, k, nullptr,
         ROWS, DDn, DDn, DDn, DDn, DDn, 0,0,0, 1,1, 1.f, 0, 0);
    // 6. V = h @ Wv + bv
    gemm(h, wt + 3*DDn*DDn, bv, nullptr, v, nullptr,
         ROWS, DDn, DDn, DDn, DDn, DDn, 0,0,0, 1,1, 1.f, 0, 0);
    // 7. V transpose -> Vt [z][768][256]
    {
        dim3 g(DDn/32, KPAD/32, NBat), b(32, 8);
        vtrans_h<<<g, b>>>(v, vt);
    }
    // 8. attn = softmax(scale * Q @ K^T)  (fused epilogue, batched)
    {
        float scale = 1.f / sqrtf((float)DDn);
        gemm(q, k, nullptr, nullptr, nullptr, at,
             SSn, SSn, DDn, DDn, DDn, KPAD,
             (long long)SSn*DDn, (long long)SSn*DDn, (long long)SSn*KPAD,
             NPIC, NBat, scale, 0, 0);
    }
    // 9. wv = attn @ V (B = Vt)
    gemm(at, vt, nullptr, nullptr, wv, nullptr,
         SSn, DDn, KPAD, KPAD, KPAD, DDn,
         (long long)SSn*KPAD, (long long)DDn*KPAD, (long long)SSn*DDn,
         1, NBat, 1.f, 0, 0);
    // 10. t = relu(wv @ Wo1 + bo1)
    gemm(wv, wt + 4*DDn*DDn, bo1, nullptr, tb, nullptr,
         ROWS, DDn, DDn, DDn, DDn, DDn, 0,0,0, 1,1, 1.f, 1, 0);
    // 11. out = t @ Wo2 + bo2
    gemm(tb, wt + 5*DDn*DDn, bo2, out, nullptr, nullptr,
         ROWS, DDn, DDn, DDn, DDn, DDn, 0,0,0, 1,1, 1.f, 0, 0);
}